// round 10
// baseline (speedup 1.0000x reference)
#include <cuda_runtime.h>
#include <math.h>

#define BATCH 65536
#define NQ 8
#define FULLM 0xffffffffu

typedef unsigned char u8;
typedef unsigned int u32;
typedef unsigned long long ull;

// ================= compile-time GF(2) algebra for CNOT ladder =================
struct M8 { u8 c[8]; };

__host__ __device__ constexpr u8 mv(const M8& m, u8 x) {
    u8 y = 0;
    for (int j = 0; j < 8; j++) if ((x >> j) & 1) y = (u8)(y ^ m.c[j]);
    return y;
}
__host__ __device__ constexpr M8 mm(const M8& a, const M8& b) {
    M8 r{}; for (int j = 0; j < 8; j++) r.c[j] = mv(a, b.c[j]); return r;
}
__host__ __device__ constexpr M8 ident() {
    M8 m{}; for (int j = 0; j < 8; j++) m.c[j] = (u8)(1u << j); return m;
}
__host__ __device__ constexpr M8 ladder() {
    M8 L = ident();
    for (int i = 0; i < 8; i++)
        for (int j = i + 1; j < 8; j++) {
            int cb = 7 - i, tb = 7 - j;
            M8 P = ident();
            P.c[cb] = (u8)((1u << cb) | (1u << tb));
            L = mm(L, P);
        }
    return L;
}
__host__ __device__ constexpr M8 minv(const M8& a) {
    u8 row[8] = {}, inv[8] = {};
    for (int i = 0; i < 8; i++) inv[i] = (u8)(1u << i);
    for (int i = 0; i < 8; i++)
        for (int j = 0; j < 8; j++)
            if ((a.c[j] >> i) & 1) row[i] = (u8)(row[i] | (1u << j));
    for (int col = 0; col < 8; col++) {
        int piv = col;
        while (!((row[piv] >> col) & 1)) piv++;
        u8 t = row[col]; row[col] = row[piv]; row[piv] = t;
        t = inv[col]; inv[col] = inv[piv]; inv[piv] = t;
        for (int i = 0; i < 8; i++)
            if (i != col && ((row[i] >> col) & 1)) { row[i] = (u8)(row[i] ^ row[col]); inv[i] = (u8)(inv[i] ^ inv[col]); }
    }
    M8 r{};
    for (int i = 0; i < 8; i++)
        for (int j = 0; j < 8; j++)
            if ((inv[i] >> j) & 1) r.c[j] = (u8)(r.c[j] | (1u << i));
    return r;
}
__host__ __device__ constexpr int par8(int x) { x ^= x >> 4; x ^= x >> 2; x ^= x >> 1; return x & 1; }

struct Masks {
    u8 v[3][8];
    u8 r[3][8];
    u8 rf[8];
};
__host__ __device__ constexpr Masks make_masks() {
    Masks mk{};
    M8 L = ladder();
    M8 C = ident();
    for (int l = 0; l < 3; l++) {
        M8 Ci = minv(C);
        for (int q = 0; q < 8; q++) {
            int B = 7 - q;
            mk.v[l][q] = mv(C, (u8)(1u << B));
            u8 rr = 0;
            for (int j = 0; j < 8; j++) if ((Ci.c[j] >> B) & 1) rr = (u8)(rr | (1u << j));
            mk.r[l][q] = rr;
        }
        C = mm(C, L);
    }
    M8 Cf = minv(C);
    for (int q = 0; q < 8; q++) {
        int B = 7 - q;
        u8 rr = 0;
        for (int j = 0; j < 8; j++) if ((Cf.c[j] >> B) & 1) rr = (u8)(rr | (1u << j));
        mk.rf[q] = rr;
    }
    return mk;
}
constexpr Masks MK = make_masks();

__host__ __device__ constexpr bool masks_ok() {
    constexpr Masks mk = make_masks();
    M8 L = ladder();
    M8 C = ident();
    for (int l = 0; l < 3; l++) {
        M8 Ci = minv(C);
        M8 P = mm(C, Ci);
        for (int j = 0; j < 8; j++) if (P.c[j] != (u8)(1u << j)) return false;
        for (int q = 0; q < 8; q++)
            if (par8(mk.v[l][q] & mk.r[l][q]) != 1) return false;
        C = mm(C, L);
    }
    return true;
}
static_assert(masks_ok(), "GF(2) mask algebra broken");

// sign LUT: SIG.v[j] bit q = parity(j & rf[q])
struct SigT { u8 v[256]; };
__host__ __device__ constexpr SigT make_sig() {
    SigT s{};
    Masks mk = make_masks();
    for (int j = 0; j < 256; j++) {
        u8 b = 0;
        for (int q = 0; q < 8; q++) if (par8(j & mk.rf[q])) b = (u8)(b | (1u << q));
        s.v[j] = b;
    }
    return s;
}
__constant__ SigT SIGC = make_sig();

// ================= f32x2 helpers =================
__device__ __forceinline__ ull fpk(float lo, float hi) {
    ull r; asm("mov.b64 %0, {%1,%2};" : "=l"(r) : "f"(lo), "f"(hi)); return r;
}
__device__ __forceinline__ void funpk(ull v, float& lo, float& hi) {
    asm("mov.b64 {%0,%1}, %2;" : "=f"(lo), "=f"(hi) : "l"(v));
}
__device__ __forceinline__ ull mul2(ull a, ull b) {
    ull d; asm("mul.rn.f32x2 %0, %1, %2;" : "=l"(d) : "l"(a), "l"(b)); return d;
}
__device__ __forceinline__ ull fma2(ull a, ull b, ull c) {
    ull d; asm("fma.rn.f32x2 %0, %1, %2, %3;" : "=l"(d) : "l"(a), "l"(b), "l"(c)); return d;
}
__device__ __forceinline__ float to_tf32(float v) {
    u32 r; asm("cvt.rna.tf32.f32 %0, %1;" : "=r"(r) : "f"(v));
    return __uint_as_float(r);
}

struct GatePack { ull AR, AIp, AIn, BRp, BRn, BIp, BIn, pad; };

// ================= device scratch =================
__device__ float    d_W1f[128 * 16];
__device__ float    d_b1f[128];
__device__ float4   d_W2f4[64 * 32];
__device__ float    d_b2f[64];
__device__ float    d_W4f[32 * 8];
__device__ float    d_b4f[32];
__device__ GatePack d_qgp[24];
__device__ float2   d_cs[BATCH * NQ];      // (cos th/2, sin th/2) per element/qubit
__device__ float    d_B[256 * 512];        // GEMM B: [k][2j]=Re U[j][k], [k][2j+1]=Im (tf32)
__device__ float    d_qout[BATCH * NQ];

// ================= precompute =================
__global__ void precompute_kernel(
    const float* W1, const float* b1, const float* g1, const float* bt1, const float* m1, const float* v1,
    const float* W2, const float* b2, const float* g2, const float* bt2, const float* m2, const float* v2,
    const float* W4, const float* b4, const float* g4, const float* bt4, const float* m4, const float* v4,
    const float* qw)
{
    int t = threadIdx.x;  // 128
    if (t < 128) {
        float a = g1[t] * rsqrtf(v1[t] + 1e-5f);
        for (int k = 0; k < 16; k++) d_W1f[t * 16 + k] = W1[t * 16 + k] * a;
        d_b1f[t] = (b1[t] - m1[t]) * a + bt1[t];
    }
    if (t < 64) {
        float a = g2[t] * rsqrtf(v2[t] + 1e-5f);
        float* w2 = (float*)d_W2f4;
        for (int k = 0; k < 128; k++) w2[t * 128 + k] = W2[t * 128 + k] * a;
        d_b2f[t] = (b2[t] - m2[t]) * a + bt2[t];
    }
    if (t < 32) {
        float a = g4[t] * rsqrtf(v4[t] + 1e-5f);
        for (int k = 0; k < 8; k++) d_W4f[t * 8 + k] = W4[t * 8 + k] * a;
        d_b4f[t] = (b4[t] - m4[t]) * a + bt4[t];
    }
    if (t < 24) {
        float sx, cx, sy, cy, sz, cz;
        sincosf(0.5f * qw[t * 3 + 0], &sx, &cx);
        sincosf(0.5f * qw[t * 3 + 1], &sy, &cy);
        sincosf(0.5f * qw[t * 3 + 2], &sz, &cz);
        float cycx = cy * cx, sysx = sy * sx, sycx = sy * cx, cysx = cy * sx;
        float ar  = cz * cycx - sz * sysx;
        float ai0 = -(cz * sysx + sz * cycx);
        float br0 = cz * sycx - sz * cysx;
        float bi  = -(cz * cysx + sz * sycx);
        Masks mk = make_masks();
        int l = t >> 3, q = t & 7;
        int rr = mk.r[l][q] & 7;
        float tau = (rr & 1) ? -1.f : 1.f;
        GatePack g;
        g.AR  = fpk(ar, ar);
        g.AIp = fpk(ai0,  tau * ai0);
        g.AIn = fpk(-ai0, -tau * ai0);
        g.BRp = fpk(br0,  tau * br0);
        g.BRn = fpk(-br0, -tau * br0);
        g.BIp = fpk(bi, bi);
        g.BIn = fpk(-bi, -bi);
        g.pad = 0;
        d_qgp[t] = g;
    }
}

// ================= verified packed gate machinery (used by build_U) =================
template<int X> struct Par {
    static constexpr int val =
        ((X >> 7) ^ (X >> 6) ^ (X >> 5) ^ (X >> 4) ^ (X >> 3) ^ (X >> 2) ^ (X >> 1) ^ X) & 1;
};

template<int V, int R>
__device__ __forceinline__ void gate2(ull X[4], ull Y[4], const GatePack* gp, int lane)
{
    static_assert(Par<V & R>::val == 1, "pair/branch masks inconsistent");
    constexpr int vl = (V >> 3) & 31, vr = V & 7;
    constexpr int rl = (R >> 3) & 31, rr = R & 7;

    ull AR  = gp->AR;
    ull BIp = gp->BIp;
    ull BIn = gp->BIn;
    bool lp = (__popc(lane & rl) & 1) != 0;
    ull AIpf = lp ? gp->AIn : gp->AIp;
    ull AInf = lp ? gp->AIp : gp->AIn;
    ull BRpf = lp ? gp->BRn : gp->BRp;
    ull BRnf = lp ? gp->BRp : gp->BRn;

    ull PX[4], PY[4];
    #pragma unroll
    for (int k = 0; k < 4; k++) {
        const int kp = k ^ (vr >> 1);
        if constexpr ((vr & 1) != 0) {
            float xlo, xhi, ylo, yhi;
            funpk(X[kp], xlo, xhi);
            funpk(Y[kp], ylo, yhi);
            if constexpr (vl != 0) {
                xlo = __shfl_xor_sync(FULLM, xlo, vl);
                xhi = __shfl_xor_sync(FULLM, xhi, vl);
                ylo = __shfl_xor_sync(FULLM, ylo, vl);
                yhi = __shfl_xor_sync(FULLM, yhi, vl);
            }
            PX[k] = fpk(xhi, xlo);
            PY[k] = fpk(yhi, ylo);
        } else {
            if constexpr (vl != 0) {
                PX[k] = __shfl_xor_sync(FULLM, X[kp], vl);
                PY[k] = __shfl_xor_sync(FULLM, Y[kp], vl);
            } else {
                PX[k] = X[kp];
                PY[k] = Y[kp];
            }
        }
    }
    #pragma unroll
    for (int k = 0; k < 4; k++) {
        const bool s0 = ((__popc((2 * k) & rr) & 1) != 0);
        ull AIx = s0 ? AIpf : AInf;
        ull AIy = s0 ? AInf : AIpf;
        ull BR  = s0 ? BRnf : BRpf;
        ull t1 = mul2(X[k], AR);
        t1 = fma2(Y[k],  AIx, t1);
        t1 = fma2(PX[k], BR,  t1);
        t1 = fma2(PY[k], BIn, t1);
        ull t2 = mul2(Y[k], AR);
        t2 = fma2(X[k],  AIy, t2);
        t2 = fma2(PY[k], BR,  t2);
        t2 = fma2(PX[k], BIp, t2);
        X[k] = t1; Y[k] = t2;
    }
}

template<int L, int Q>
__device__ __forceinline__ void gate(ull X[4], ull Y[4], const GatePack* gs, int lane)
{
    gate2<MK.v[L][Q], MK.r[L][Q]>(X, Y, gs + (L * 8 + Q), lane);
}

// ================= build U columns: warp k simulates basis state k =================
__global__ void __launch_bounds__(256) build_U_kernel()
{
    __shared__ GatePack gs[24];
    int t = threadIdx.x;
    if (t < 192) ((ull*)gs)[t] = ((const ull*)d_qgp)[t];
    __syncthreads();

    int k = blockIdx.x * 8 + (t >> 5);   // basis index 0..255
    int lane = t & 31;

    ull X[4], Y[4];
    #pragma unroll
    for (int p = 0; p < 4; p++) {
        int j0 = lane * 8 + 2 * p, j1 = j0 + 1;
        X[p] = fpk(j0 == k ? 1.f : 0.f, j1 == k ? 1.f : 0.f);
        Y[p] = fpk(0.f, 0.f);
    }

    gate<0,0>(X, Y, gs, lane); gate<0,1>(X, Y, gs, lane); gate<0,2>(X, Y, gs, lane); gate<0,3>(X, Y, gs, lane);
    gate<0,4>(X, Y, gs, lane); gate<0,5>(X, Y, gs, lane); gate<0,6>(X, Y, gs, lane); gate<0,7>(X, Y, gs, lane);
    gate<1,0>(X, Y, gs, lane); gate<1,1>(X, Y, gs, lane); gate<1,2>(X, Y, gs, lane); gate<1,3>(X, Y, gs, lane);
    gate<1,4>(X, Y, gs, lane); gate<1,5>(X, Y, gs, lane); gate<1,6>(X, Y, gs, lane); gate<1,7>(X, Y, gs, lane);
    gate<2,0>(X, Y, gs, lane); gate<2,1>(X, Y, gs, lane); gate<2,2>(X, Y, gs, lane); gate<2,3>(X, Y, gs, lane);
    gate<2,4>(X, Y, gs, lane); gate<2,5>(X, Y, gs, lane); gate<2,6>(X, Y, gs, lane); gate<2,7>(X, Y, gs, lane);

    // write row k of B: B[k][2j]=Re(s_j), [2j+1]=Im(s_j); j = lane*8 + slot
    #pragma unroll
    for (int p = 0; p < 4; p++) {
        float x0, x1, y0, y1;
        funpk(X[p], x0, x1);
        funpk(Y[p], y0, y1);
        float4 v = make_float4(to_tf32(x0), to_tf32(y0), to_tf32(x1), to_tf32(y1));
        *(float4*)&d_B[k * 512 + lane * 16 + p * 4] = v;
    }
}

// ================= front MLP: x[B,16] -> cs pairs =================
#define FB 1024
#define FROWS 64
#define FTILE 16

__global__ void __launch_bounds__(128) front_kernel(const float* __restrict__ x,
                                                    const float* __restrict__ W3,
                                                    const float* __restrict__ b3)
{
    __shared__ float4 w2s4[64 * 32];
    __shared__ float4 w3s4[8 * 16];
    __shared__ float4 xs4[FTILE][4];
    __shared__ float4 h1s4[FTILE][32];
    __shared__ float4 h2s4[FTILE][16];
    __shared__ float  b2s[64], b3s[8];

    int t = threadIdx.x;  // 128
    for (int i = t; i < 64 * 32; i += 128) {
        int o = i >> 5, k = i & 31;
        w2s4[(o << 5) + (k ^ (o & 7))] = d_W2f4[i];
    }
    {
        const float4* W34 = (const float4*)W3;
        if (t < 8 * 16) w3s4[t] = W34[t];
        if (t < 64) b2s[t] = d_b2f[t];
        if (t < 8)  b3s[t] = b3[t];
    }
    float w1[16];
    #pragma unroll
    for (int k = 0; k < 16; k++) w1[k] = d_W1f[t * 16 + k];
    float bb1 = d_b1f[t];
    __syncthreads();

    const float4* x4 = (const float4*)x;
    int base = blockIdx.x * FROWS;

    for (int it = 0; it < FROWS / FTILE; it++) {
        int rbase = base + it * FTILE;
        if (t < FTILE * 4) xs4[t >> 2][t & 3] = x4[(rbase + (t >> 2)) * 4 + (t & 3)];
        __syncthreads();

        #pragma unroll
        for (int r = 0; r < FTILE; r++) {
            float4 xa = xs4[r][0], xb = xs4[r][1], xc = xs4[r][2], xd = xs4[r][3];
            float a = bb1;
            a += w1[0]*xa.x + w1[1]*xa.y + w1[2]*xa.z + w1[3]*xa.w;
            a += w1[4]*xb.x + w1[5]*xb.y + w1[6]*xb.z + w1[7]*xb.w;
            a += w1[8]*xc.x + w1[9]*xc.y + w1[10]*xc.z + w1[11]*xc.w;
            a += w1[12]*xd.x + w1[13]*xd.y + w1[14]*xd.z + w1[15]*xd.w;
            ((float*)&h1s4[r][0])[t] = fmaxf(a, 0.f);
        }
        __syncthreads();

        {
            int o = t & 63, half = t >> 6;
            int obase = o << 5, osw = o & 7;
            float acc[8];
            #pragma unroll
            for (int rr = 0; rr < 8; rr++) acc[rr] = b2s[o];
            #pragma unroll 4
            for (int k4 = 0; k4 < 32; k4++) {
                float4 w = w2s4[obase + (k4 ^ osw)];
                #pragma unroll
                for (int rr = 0; rr < 8; rr++) {
                    float4 h = h1s4[half * 8 + rr][k4];
                    acc[rr] += w.x*h.x + w.y*h.y + w.z*h.z + w.w*h.w;
                }
            }
            #pragma unroll
            for (int rr = 0; rr < 8; rr++)
                ((float*)&h2s4[half * 8 + rr][0])[o] = fmaxf(acc[rr], 0.f);
        }
        __syncthreads();

        {
            int r = t >> 3, o = t & 7;
            float a = b3s[o];
            #pragma unroll
            for (int k4 = 0; k4 < 16; k4++) {
                float4 w = w3s4[o * 16 + k4];
                float4 h = h2s4[r][k4];
                a += w.x*h.x + w.y*h.y + w.z*h.z + w.w*h.w;
            }
            float pre = tanhf(a);
            float sc, cc;
            __sincosf(0.5f * pre, &sc, &cc);
            d_cs[(rbase + r) * 8 + o] = make_float2(cc, sc);
        }
        __syncthreads();
    }
}

// ================= GEMM: S = A * B, fused |.|^2 + parity reduce =================
// A[e][i] = prod_q (bit(i,7-q) ? -s_q : c_q), built in-smem from d_cs (tf32).
// B from d_B. M=65536, N=512, K=256. BM=128, BN=64, BK=32, 8 warps, warp 32x32.
#define AS_STR 36
#define BS_STR 72

__global__ void __launch_bounds__(256) gemm_kernel()
{
    __shared__ float As[128 * AS_STR];   // [row][k] 18.4KB
    __shared__ float Bs[32 * BS_STR];    // [k][n]    9.2KB
    __shared__ float outs[128 * 8];      // 4KB

    int t = threadIdx.x;
    int warp = t >> 5, lane = t & 31;
    int gid = lane >> 2, tig = lane & 3;
    int wm = warp & 3, wn = warp >> 2;   // wm: 4 x 32 rows, wn: 2 x 32 cols
    int eb = blockIdx.x * 128;

    // cs for this thread's A-build row
    int rrow = t >> 1, h = t & 1;
    float2 cs[8];
    #pragma unroll
    for (int q = 0; q < 8; q++) cs[q] = d_cs[(eb + rrow) * 8 + q];

    for (int i = t; i < 128 * 8; i += 256) outs[i] = 0.f;

    float outp[4][8];
    #pragma unroll
    for (int i = 0; i < 4; i++)
        #pragma unroll
        for (int q = 0; q < 8; q++) outp[i][q] = 0.f;

    const float4* Bg4 = (const float4*)d_B;

    for (int ntile = 0; ntile < 8; ntile++) {
        float acc[2][4][4];
        #pragma unroll
        for (int mt = 0; mt < 2; mt++)
            #pragma unroll
            for (int nf = 0; nf < 4; nf++)
                #pragma unroll
                for (int rr = 0; rr < 4; rr++) acc[mt][nf][rr] = 0.f;

        for (int chunk = 0; chunk < 8; chunk++) {
            // ---- build A tile: row rrow, k_local = h*16 .. h*16+15 ----
            {
                int hi = chunk * 2 + h;   // bits 7..4 of amp index
                float fhi = 1.f;
                fhi *= (hi & 8) ? -cs[0].y : cs[0].x;
                fhi *= (hi & 4) ? -cs[1].y : cs[1].x;
                fhi *= (hi & 2) ? -cs[2].y : cs[2].x;
                fhi *= (hi & 1) ? -cs[3].y : cs[3].x;
                float A1[2], A2[4], A3[8], A4[16];
                A1[0] = fhi * cs[4].x;  A1[1] = -fhi * cs[4].y;
                #pragma unroll
                for (int i = 0; i < 4; i++)  A2[i] = A1[i >> 1] * ((i & 1) ? -cs[5].y : cs[5].x);
                #pragma unroll
                for (int i = 0; i < 8; i++)  A3[i] = A2[i >> 1] * ((i & 1) ? -cs[6].y : cs[6].x);
                #pragma unroll
                for (int i = 0; i < 16; i++) A4[i] = A3[i >> 1] * ((i & 1) ? -cs[7].y : cs[7].x);
                #pragma unroll
                for (int i = 0; i < 16; i++)
                    As[rrow * AS_STR + h * 16 + i] = to_tf32(A4[i]);
            }
            // ---- load B tile: rows chunk*32.., cols ntile*64.. ----
            #pragma unroll
            for (int p = 0; p < 2; p++) {
                int kl = p * 16 + (t >> 4);
                int c4 = t & 15;
                float4 v = Bg4[(chunk * 32 + kl) * 128 + ntile * 16 + c4];
                *(float4*)&Bs[kl * BS_STR + c4 * 4] = v;
            }
            __syncthreads();

            // ---- mma ----
            #pragma unroll
            for (int kk = 0; kk < 4; kk++) {
                u32 a[2][4];
                #pragma unroll
                for (int mt = 0; mt < 2; mt++) {
                    int row = wm * 32 + mt * 16 + gid;
                    int kc = kk * 8 + tig;
                    a[mt][0] = __float_as_uint(As[row * AS_STR + kc]);
                    a[mt][1] = __float_as_uint(As[(row + 8) * AS_STR + kc]);
                    a[mt][2] = __float_as_uint(As[row * AS_STR + kc + 4]);
                    a[mt][3] = __float_as_uint(As[(row + 8) * AS_STR + kc + 4]);
                }
                u32 b[4][2];
                #pragma unroll
                for (int nf = 0; nf < 4; nf++) {
                    int col = wn * 32 + nf * 8 + gid;
                    b[nf][0] = __float_as_uint(Bs[(kk * 8 + tig) * BS_STR + col]);
                    b[nf][1] = __float_as_uint(Bs[(kk * 8 + tig + 4) * BS_STR + col]);
                }
                #pragma unroll
                for (int mt = 0; mt < 2; mt++)
                    #pragma unroll
                    for (int nf = 0; nf < 4; nf++) {
                        asm volatile(
                            "mma.sync.aligned.m16n8k8.row.col.f32.tf32.tf32.f32 "
                            "{%0,%1,%2,%3}, {%4,%5,%6,%7}, {%8,%9}, {%0,%1,%2,%3};"
                            : "+f"(acc[mt][nf][0]), "+f"(acc[mt][nf][1]),
                              "+f"(acc[mt][nf][2]), "+f"(acc[mt][nf][3])
                            : "r"(a[mt][0]), "r"(a[mt][1]), "r"(a[mt][2]), "r"(a[mt][3]),
                              "r"(b[nf][0]), "r"(b[nf][1]));
                    }
            }
            __syncthreads();
        }

        // ---- epilogue for this ntile: p = re^2+im^2 (adjacent cols in-thread) ----
        #pragma unroll
        for (int mt = 0; mt < 2; mt++)
            #pragma unroll
            for (int nf = 0; nf < 4; nf++) {
                int j = ntile * 32 + wn * 16 + nf * 4 + tig;   // prob index 0..255
                u8 sb = SIGC.v[j];
                float p0 = acc[mt][nf][0] * acc[mt][nf][0] + acc[mt][nf][1] * acc[mt][nf][1];
                float p1 = acc[mt][nf][2] * acc[mt][nf][2] + acc[mt][nf][3] * acc[mt][nf][3];
                #pragma unroll
                for (int q = 0; q < 8; q++) {
                    float s0 = ((sb >> q) & 1) ? -p0 : p0;
                    float s1 = ((sb >> q) & 1) ? -p1 : p1;
                    outp[mt * 2 + 0][q] += s0;
                    outp[mt * 2 + 1][q] += s1;
                }
            }
    }

    // ---- block reduce over (wn, tig) sharing same rows ----
    #pragma unroll
    for (int idx = 0; idx < 4; idx++) {
        int row = wm * 32 + idx * 8 + gid;
        #pragma unroll
        for (int q = 0; q < 8; q++)
            atomicAdd(&outs[row * 8 + q], outp[idx][q]);
    }
    __syncthreads();
    {
        float4 v = *(float4*)&outs[t * 4];
        ((float4*)d_qout)[eb * 2 + t] = v;   // eb*8/4 = eb*2
    }
}

// ================= tail MLP: qout[B,8] -> out[B,1] =================
__global__ void __launch_bounds__(256) tail_kernel(const float* __restrict__ W5, const float* __restrict__ b5,
                                                   const float* __restrict__ W6, const float* __restrict__ b6,
                                                   float* __restrict__ out)
{
    __shared__ float w4s[32 * 8], b4s[32], w5s[16 * 32], b5s[16], w6s[16], b6s;
    int t = threadIdx.x;  // 256
    w4s[t] = d_W4f[t];
    if (t < 32) b4s[t] = d_b4f[t];
    for (int i = t; i < 16 * 32; i += 256) w5s[i] = W5[i];
    if (t < 16) { b5s[t] = b5[t]; w6s[t] = W6[t]; }
    if (t == 0) b6s = b6[0];
    __syncthreads();

    int e = blockIdx.x * 256 + t;
    float4 qa = *(const float4*)&d_qout[e * 8];
    float4 qb = *(const float4*)&d_qout[e * 8 + 4];
    float q[8] = {qa.x, qa.y, qa.z, qa.w, qb.x, qb.y, qb.z, qb.w};

    float h5[16];
    #pragma unroll
    for (int j = 0; j < 16; j++) h5[j] = b5s[j];
    #pragma unroll
    for (int o = 0; o < 32; o++) {
        float a = b4s[o];
        #pragma unroll
        for (int k = 0; k < 8; k++) a += w4s[o * 8 + k] * q[k];
        a = fmaxf(a, 0.f);
        #pragma unroll
        for (int j = 0; j < 16; j++) h5[j] += w5s[j * 32 + o] * a;
    }
    float o6 = b6s;
    #pragma unroll
    for (int j = 0; j < 16; j++) o6 += fmaxf(h5[j], 0.f) * w6s[j];
    out[e] = o6;
}

// ================= launch =================
extern "C" void kernel_launch(void* const* d_in, const int* in_sizes, int n_in,
                              void* d_out, int out_size)
{
    const float* x   = (const float*)d_in[0];
    const float* W1  = (const float*)d_in[1];
    const float* b1  = (const float*)d_in[2];
    const float* g1  = (const float*)d_in[3];
    const float* bt1 = (const float*)d_in[4];
    const float* m1  = (const float*)d_in[5];
    const float* v1  = (const float*)d_in[6];
    const float* W2  = (const float*)d_in[7];
    const float* b2  = (const float*)d_in[8];
    const float* g2  = (const float*)d_in[9];
    const float* bt2 = (const float*)d_in[10];
    const float* m2  = (const float*)d_in[11];
    const float* v2  = (const float*)d_in[12];
    const float* W3  = (const float*)d_in[13];
    const float* b3  = (const float*)d_in[14];
    const float* qw  = (const float*)d_in[15];
    const float* W4  = (const float*)d_in[16];
    const float* b4  = (const float*)d_in[17];
    const float* g4  = (const float*)d_in[18];
    const float* bt4 = (const float*)d_in[19];
    const float* m4  = (const float*)d_in[20];
    const float* v4_ = (const float*)d_in[21];
    const float* W5  = (const float*)d_in[22];
    const float* b5  = (const float*)d_in[23];
    const float* W6  = (const float*)d_in[24];
    const float* b6  = (const float*)d_in[25];

    precompute_kernel<<<1, 128>>>(W1, b1, g1, bt1, m1, v1,
                                  W2, b2, g2, bt2, m2, v2,
                                  W4, b4, g4, bt4, m4, v4_, qw);
    build_U_kernel<<<32, 256>>>();
    front_kernel<<<FB, 128>>>(x, W3, b3);
    gemm_kernel<<<BATCH / 128, 256>>>();
    tail_kernel<<<BATCH / 256, 256>>>(W5, b5, W6, b6, (float*)d_out);
}

// round 11
// speedup vs baseline: 1.3008x; 1.3008x over previous
#include <cuda_runtime.h>
#include <cuda_fp16.h>
#include <math.h>

#define BATCH 65536
#define NQ 8
#define FULLM 0xffffffffu

typedef unsigned char u8;
typedef unsigned int u32;
typedef unsigned long long ull;

// ================= compile-time GF(2) algebra for CNOT ladder =================
struct M8 { u8 c[8]; };

__host__ __device__ constexpr u8 mv(const M8& m, u8 x) {
    u8 y = 0;
    for (int j = 0; j < 8; j++) if ((x >> j) & 1) y = (u8)(y ^ m.c[j]);
    return y;
}
__host__ __device__ constexpr M8 mm(const M8& a, const M8& b) {
    M8 r{}; for (int j = 0; j < 8; j++) r.c[j] = mv(a, b.c[j]); return r;
}
__host__ __device__ constexpr M8 ident() {
    M8 m{}; for (int j = 0; j < 8; j++) m.c[j] = (u8)(1u << j); return m;
}
__host__ __device__ constexpr M8 ladder() {
    M8 L = ident();
    for (int i = 0; i < 8; i++)
        for (int j = i + 1; j < 8; j++) {
            int cb = 7 - i, tb = 7 - j;
            M8 P = ident();
            P.c[cb] = (u8)((1u << cb) | (1u << tb));
            L = mm(L, P);
        }
    return L;
}
__host__ __device__ constexpr M8 minv(const M8& a) {
    u8 row[8] = {}, inv[8] = {};
    for (int i = 0; i < 8; i++) inv[i] = (u8)(1u << i);
    for (int i = 0; i < 8; i++)
        for (int j = 0; j < 8; j++)
            if ((a.c[j] >> i) & 1) row[i] = (u8)(row[i] | (1u << j));
    for (int col = 0; col < 8; col++) {
        int piv = col;
        while (!((row[piv] >> col) & 1)) piv++;
        u8 t = row[col]; row[col] = row[piv]; row[piv] = t;
        t = inv[col]; inv[col] = inv[piv]; inv[piv] = t;
        for (int i = 0; i < 8; i++)
            if (i != col && ((row[i] >> col) & 1)) { row[i] = (u8)(row[i] ^ row[col]); inv[i] = (u8)(inv[i] ^ inv[col]); }
    }
    M8 r{};
    for (int i = 0; i < 8; i++)
        for (int j = 0; j < 8; j++)
            if ((inv[i] >> j) & 1) r.c[j] = (u8)(r.c[j] | (1u << i));
    return r;
}
__host__ __device__ constexpr int par8(int x) { x ^= x >> 4; x ^= x >> 2; x ^= x >> 1; return x & 1; }

struct Masks {
    u8 v[3][8];
    u8 r[3][8];
    u8 rf[8];
};
__host__ __device__ constexpr Masks make_masks() {
    Masks mk{};
    M8 L = ladder();
    M8 C = ident();
    for (int l = 0; l < 3; l++) {
        M8 Ci = minv(C);
        for (int q = 0; q < 8; q++) {
            int B = 7 - q;
            mk.v[l][q] = mv(C, (u8)(1u << B));
            u8 rr = 0;
            for (int j = 0; j < 8; j++) if ((Ci.c[j] >> B) & 1) rr = (u8)(rr | (1u << j));
            mk.r[l][q] = rr;
        }
        C = mm(C, L);
    }
    M8 Cf = minv(C);
    for (int q = 0; q < 8; q++) {
        int B = 7 - q;
        u8 rr = 0;
        for (int j = 0; j < 8; j++) if ((Cf.c[j] >> B) & 1) rr = (u8)(rr | (1u << j));
        mk.rf[q] = rr;
    }
    return mk;
}
constexpr Masks MK = make_masks();

__host__ __device__ constexpr bool masks_ok() {
    constexpr Masks mk = make_masks();
    M8 L = ladder();
    M8 C = ident();
    for (int l = 0; l < 3; l++) {
        M8 Ci = minv(C);
        M8 P = mm(C, Ci);
        for (int j = 0; j < 8; j++) if (P.c[j] != (u8)(1u << j)) return false;
        for (int q = 0; q < 8; q++)
            if (par8(mk.v[l][q] & mk.r[l][q]) != 1) return false;
        C = mm(C, L);
    }
    return true;
}
static_assert(masks_ok(), "GF(2) mask algebra broken");

// sign LUT: SIG.v[j] bit q = parity(j & rf[q])
struct SigT { u8 v[256]; };
__host__ __device__ constexpr SigT make_sig() {
    SigT s{};
    Masks mk = make_masks();
    for (int j = 0; j < 256; j++) {
        u8 b = 0;
        for (int q = 0; q < 8; q++) if (par8(j & mk.rf[q])) b = (u8)(b | (1u << q));
        s.v[j] = b;
    }
    return s;
}
__constant__ SigT SIGC = make_sig();

// ================= f32x2 helpers =================
__device__ __forceinline__ ull fpk(float lo, float hi) {
    ull r; asm("mov.b64 %0, {%1,%2};" : "=l"(r) : "f"(lo), "f"(hi)); return r;
}
__device__ __forceinline__ void funpk(ull v, float& lo, float& hi) {
    asm("mov.b64 {%0,%1}, %2;" : "=f"(lo), "=f"(hi) : "l"(v));
}
__device__ __forceinline__ ull mul2(ull a, ull b) {
    ull d; asm("mul.rn.f32x2 %0, %1, %2;" : "=l"(d) : "l"(a), "l"(b)); return d;
}
__device__ __forceinline__ ull fma2(ull a, ull b, ull c) {
    ull d; asm("fma.rn.f32x2 %0, %1, %2, %3;" : "=l"(d) : "l"(a), "l"(b), "l"(c)); return d;
}

struct GatePack { ull AR, AIp, AIn, BRp, BRn, BIp, BIn, pad; };

// ================= device scratch =================
__device__ float    d_W1f[128 * 16];
__device__ float    d_b1f[128];
__device__ float4   d_W2f4[64 * 32];
__device__ float    d_b2f[64];
__device__ float    d_W4f[32 * 8];
__device__ float    d_b4f[32];
__device__ GatePack d_qgp[24];
__device__ float2   d_cs[BATCH * NQ];               // (cos th/2, sin th/2)
__device__ uint4    d_AhR[BATCH * 32];              // A fp16 [BATCH][256]  (32MB)
__device__ uint4    d_BhR[512 * 32];                // B fp16 [512 n][256 k] (256KB)
__device__ float    d_qout[BATCH * NQ];

// ================= precompute =================
__global__ void precompute_kernel(
    const float* W1, const float* b1, const float* g1, const float* bt1, const float* m1, const float* v1,
    const float* W2, const float* b2, const float* g2, const float* bt2, const float* m2, const float* v2,
    const float* W4, const float* b4, const float* g4, const float* bt4, const float* m4, const float* v4,
    const float* qw)
{
    int t = threadIdx.x;  // 128
    if (t < 128) {
        float a = g1[t] * rsqrtf(v1[t] + 1e-5f);
        for (int k = 0; k < 16; k++) d_W1f[t * 16 + k] = W1[t * 16 + k] * a;
        d_b1f[t] = (b1[t] - m1[t]) * a + bt1[t];
    }
    if (t < 64) {
        float a = g2[t] * rsqrtf(v2[t] + 1e-5f);
        float* w2 = (float*)d_W2f4;
        for (int k = 0; k < 128; k++) w2[t * 128 + k] = W2[t * 128 + k] * a;
        d_b2f[t] = (b2[t] - m2[t]) * a + bt2[t];
    }
    if (t < 32) {
        float a = g4[t] * rsqrtf(v4[t] + 1e-5f);
        for (int k = 0; k < 8; k++) d_W4f[t * 8 + k] = W4[t * 8 + k] * a;
        d_b4f[t] = (b4[t] - m4[t]) * a + bt4[t];
    }
    if (t < 24) {
        float sx, cx, sy, cy, sz, cz;
        sincosf(0.5f * qw[t * 3 + 0], &sx, &cx);
        sincosf(0.5f * qw[t * 3 + 1], &sy, &cy);
        sincosf(0.5f * qw[t * 3 + 2], &sz, &cz);
        float cycx = cy * cx, sysx = sy * sx, sycx = sy * cx, cysx = cy * sx;
        float ar  = cz * cycx - sz * sysx;
        float ai0 = -(cz * sysx + sz * cycx);
        float br0 = cz * sycx - sz * cysx;
        float bi  = -(cz * cysx + sz * sycx);
        Masks mk = make_masks();
        int l = t >> 3, q = t & 7;
        int rr = mk.r[l][q] & 7;
        float tau = (rr & 1) ? -1.f : 1.f;
        GatePack g;
        g.AR  = fpk(ar, ar);
        g.AIp = fpk(ai0,  tau * ai0);
        g.AIn = fpk(-ai0, -tau * ai0);
        g.BRp = fpk(br0,  tau * br0);
        g.BRn = fpk(-br0, -tau * br0);
        g.BIp = fpk(bi, bi);
        g.BIn = fpk(-bi, -bi);
        g.pad = 0;
        d_qgp[t] = g;
    }
}

// ================= packed gate machinery (verified) =================
template<int X> struct Par {
    static constexpr int val =
        ((X >> 7) ^ (X >> 6) ^ (X >> 5) ^ (X >> 4) ^ (X >> 3) ^ (X >> 2) ^ (X >> 1) ^ X) & 1;
};

template<int V, int R>
__device__ __forceinline__ void gate2(ull X[4], ull Y[4], const GatePack* gp, int lane)
{
    static_assert(Par<V & R>::val == 1, "pair/branch masks inconsistent");
    constexpr int vl = (V >> 3) & 31, vr = V & 7;
    constexpr int rl = (R >> 3) & 31, rr = R & 7;

    ull AR  = gp->AR;
    ull BIp = gp->BIp;
    ull BIn = gp->BIn;
    bool lp = (__popc(lane & rl) & 1) != 0;
    ull AIpf = lp ? gp->AIn : gp->AIp;
    ull AInf = lp ? gp->AIp : gp->AIn;
    ull BRpf = lp ? gp->BRn : gp->BRp;
    ull BRnf = lp ? gp->BRp : gp->BRn;

    ull PX[4], PY[4];
    #pragma unroll
    for (int k = 0; k < 4; k++) {
        const int kp = k ^ (vr >> 1);
        if constexpr ((vr & 1) != 0) {
            float xlo, xhi, ylo, yhi;
            funpk(X[kp], xlo, xhi);
            funpk(Y[kp], ylo, yhi);
            if constexpr (vl != 0) {
                xlo = __shfl_xor_sync(FULLM, xlo, vl);
                xhi = __shfl_xor_sync(FULLM, xhi, vl);
                ylo = __shfl_xor_sync(FULLM, ylo, vl);
                yhi = __shfl_xor_sync(FULLM, yhi, vl);
            }
            PX[k] = fpk(xhi, xlo);
            PY[k] = fpk(yhi, ylo);
        } else {
            if constexpr (vl != 0) {
                PX[k] = __shfl_xor_sync(FULLM, X[kp], vl);
                PY[k] = __shfl_xor_sync(FULLM, Y[kp], vl);
            } else {
                PX[k] = X[kp];
                PY[k] = Y[kp];
            }
        }
    }
    #pragma unroll
    for (int k = 0; k < 4; k++) {
        const bool s0 = ((__popc((2 * k) & rr) & 1) != 0);
        ull AIx = s0 ? AIpf : AInf;
        ull AIy = s0 ? AInf : AIpf;
        ull BR  = s0 ? BRnf : BRpf;
        ull t1 = mul2(X[k], AR);
        t1 = fma2(Y[k],  AIx, t1);
        t1 = fma2(PX[k], BR,  t1);
        t1 = fma2(PY[k], BIn, t1);
        ull t2 = mul2(Y[k], AR);
        t2 = fma2(X[k],  AIy, t2);
        t2 = fma2(PY[k], BR,  t2);
        t2 = fma2(PX[k], BIp, t2);
        X[k] = t1; Y[k] = t2;
    }
}

template<int L, int Q>
__device__ __forceinline__ void gate(ull X[4], ull Y[4], const GatePack* gs, int lane)
{
    gate2<MK.v[L][Q], MK.r[L][Q]>(X, Y, gs + (L * 8 + Q), lane);
}

// ================= build U: warp k simulates basis k; B stored [n=512][k=256] fp16 =================
__global__ void __launch_bounds__(256) build_U_kernel()
{
    __shared__ GatePack gs[24];
    __shared__ half Bst[512][8];   // staging: [n][warp] for this block's 8 k-columns
    int t = threadIdx.x;
    if (t < 192) ((ull*)gs)[t] = ((const ull*)d_qgp)[t];
    __syncthreads();

    int w = t >> 5;
    int k = blockIdx.x * 8 + w;
    int lane = t & 31;

    ull X[4], Y[4];
    #pragma unroll
    for (int p = 0; p < 4; p++) {
        int j0 = lane * 8 + 2 * p, j1 = j0 + 1;
        X[p] = fpk(j0 == k ? 1.f : 0.f, j1 == k ? 1.f : 0.f);
        Y[p] = fpk(0.f, 0.f);
    }

    gate<0,0>(X, Y, gs, lane); gate<0,1>(X, Y, gs, lane); gate<0,2>(X, Y, gs, lane); gate<0,3>(X, Y, gs, lane);
    gate<0,4>(X, Y, gs, lane); gate<0,5>(X, Y, gs, lane); gate<0,6>(X, Y, gs, lane); gate<0,7>(X, Y, gs, lane);
    gate<1,0>(X, Y, gs, lane); gate<1,1>(X, Y, gs, lane); gate<1,2>(X, Y, gs, lane); gate<1,3>(X, Y, gs, lane);
    gate<1,4>(X, Y, gs, lane); gate<1,5>(X, Y, gs, lane); gate<1,6>(X, Y, gs, lane); gate<1,7>(X, Y, gs, lane);
    gate<2,0>(X, Y, gs, lane); gate<2,1>(X, Y, gs, lane); gate<2,2>(X, Y, gs, lane); gate<2,3>(X, Y, gs, lane);
    gate<2,4>(X, Y, gs, lane); gate<2,5>(X, Y, gs, lane); gate<2,6>(X, Y, gs, lane); gate<2,7>(X, Y, gs, lane);

    // stage: n = 2j (+1 for Im), this warp's column w
    #pragma unroll
    for (int p = 0; p < 4; p++) {
        float x0, x1, y0, y1;
        funpk(X[p], x0, x1);
        funpk(Y[p], y0, y1);
        int j0 = lane * 8 + 2 * p, j1 = j0 + 1;
        Bst[2 * j0][w]     = __float2half_rn(x0);
        Bst[2 * j0 + 1][w] = __float2half_rn(y0);
        Bst[2 * j1][w]     = __float2half_rn(x1);
        Bst[2 * j1 + 1][w] = __float2half_rn(y1);
    }
    __syncthreads();

    half* Bh = (half*)d_BhR;
    for (int i = t; i < 512; i += 256)
        *(uint4*)&Bh[i * 256 + blockIdx.x * 8] = *(uint4*)&Bst[i][0];
}

// ================= front MLP: x[B,16] -> cs pairs =================
#define FB 2048
#define FROWS 32
#define FTILE 16

__global__ void __launch_bounds__(128) front_kernel(const float* __restrict__ x,
                                                    const float* __restrict__ W3,
                                                    const float* __restrict__ b3)
{
    __shared__ float4 w2s4[64 * 32];
    __shared__ float4 w3s4[8 * 16];
    __shared__ float4 xs4[FTILE][4];
    __shared__ float4 h1s4[FTILE][32];
    __shared__ float4 h2s4[FTILE][16];
    __shared__ float  b2s[64], b3s[8];

    int t = threadIdx.x;  // 128
    for (int i = t; i < 64 * 32; i += 128) {
        int o = i >> 5, k = i & 31;
        w2s4[(o << 5) + (k ^ (o & 7))] = d_W2f4[i];
    }
    {
        const float4* W34 = (const float4*)W3;
        if (t < 8 * 16) w3s4[t] = W34[t];
        if (t < 64) b2s[t] = d_b2f[t];
        if (t < 8)  b3s[t] = b3[t];
    }
    float w1[16];
    #pragma unroll
    for (int k = 0; k < 16; k++) w1[k] = d_W1f[t * 16 + k];
    float bb1 = d_b1f[t];
    __syncthreads();

    const float4* x4 = (const float4*)x;
    int base = blockIdx.x * FROWS;

    for (int it = 0; it < FROWS / FTILE; it++) {
        int rbase = base + it * FTILE;
        if (t < FTILE * 4) xs4[t >> 2][t & 3] = x4[(rbase + (t >> 2)) * 4 + (t & 3)];
        __syncthreads();

        #pragma unroll
        for (int r = 0; r < FTILE; r++) {
            float4 xa = xs4[r][0], xb = xs4[r][1], xc = xs4[r][2], xd = xs4[r][3];
            float a = bb1;
            a += w1[0]*xa.x + w1[1]*xa.y + w1[2]*xa.z + w1[3]*xa.w;
            a += w1[4]*xb.x + w1[5]*xb.y + w1[6]*xb.z + w1[7]*xb.w;
            a += w1[8]*xc.x + w1[9]*xc.y + w1[10]*xc.z + w1[11]*xc.w;
            a += w1[12]*xd.x + w1[13]*xd.y + w1[14]*xd.z + w1[15]*xd.w;
            ((float*)&h1s4[r][0])[t] = fmaxf(a, 0.f);
        }
        __syncthreads();

        {
            int o = t & 63, half_ = t >> 6;
            int obase = o << 5, osw = o & 7;
            float acc[8];
            #pragma unroll
            for (int rr = 0; rr < 8; rr++) acc[rr] = b2s[o];
            #pragma unroll 4
            for (int k4 = 0; k4 < 32; k4++) {
                float4 w = w2s4[obase + (k4 ^ osw)];
                #pragma unroll
                for (int rr = 0; rr < 8; rr++) {
                    float4 h = h1s4[half_ * 8 + rr][k4];
                    acc[rr] += w.x*h.x + w.y*h.y + w.z*h.z + w.w*h.w;
                }
            }
            #pragma unroll
            for (int rr = 0; rr < 8; rr++)
                ((float*)&h2s4[half_ * 8 + rr][0])[o] = fmaxf(acc[rr], 0.f);
        }
        __syncthreads();

        {
            int r = t >> 3, o = t & 7;
            float a = b3s[o];
            #pragma unroll
            for (int k4 = 0; k4 < 16; k4++) {
                float4 w = w3s4[o * 16 + k4];
                float4 h = h2s4[r][k4];
                a += w.x*h.x + w.y*h.y + w.z*h.z + w.w*h.w;
            }
            float pre = tanhf(a);
            float sc, cc;
            __sincosf(0.5f * pre, &sc, &cc);
            d_cs[(rbase + r) * 8 + o] = make_float2(cc, sc);
        }
        __syncthreads();
    }
}

// ================= abuild: materialize A[e][k] fp16 from cs (kron tree) =================
__global__ void __launch_bounds__(256) abuild_kernel()
{
    int t = threadIdx.x;
    int e = blockIdx.x * 16 + (t >> 4);
    int sub = t & 15;   // k bits 7..4

    float2 cs[8];
    #pragma unroll
    for (int q = 0; q < 8; q++) cs[q] = d_cs[e * 8 + q];

    float fhi = 1.f;
    fhi *= (sub & 8) ? -cs[0].y : cs[0].x;
    fhi *= (sub & 4) ? -cs[1].y : cs[1].x;
    fhi *= (sub & 2) ? -cs[2].y : cs[2].x;
    fhi *= (sub & 1) ? -cs[3].y : cs[3].x;

    float A1[2], A2[4], A3[8], A4[16];
    A1[0] = fhi * cs[4].x;  A1[1] = -fhi * cs[4].y;
    #pragma unroll
    for (int i = 0; i < 4; i++)  A2[i] = A1[i >> 1] * ((i & 1) ? -cs[5].y : cs[5].x);
    #pragma unroll
    for (int i = 0; i < 8; i++)  A3[i] = A2[i >> 1] * ((i & 1) ? -cs[6].y : cs[6].x);
    #pragma unroll
    for (int i = 0; i < 16; i++) A4[i] = A3[i >> 1] * ((i & 1) ? -cs[7].y : cs[7].x);

    half2 h2v[8];
    #pragma unroll
    for (int i = 0; i < 8; i++) h2v[i] = __floats2half2_rn(A4[2 * i], A4[2 * i + 1]);

    half* Ah = (half*)d_AhR;
    uint4* dst = (uint4*)&Ah[e * 256 + sub * 16];
    dst[0] = *(uint4*)&h2v[0];
    dst[1] = *(uint4*)&h2v[4];
}

// ================= fp16 GEMM: S = A*B, fused |.|^2 + parity reduce =================
// A [65536][256] fp16 (global), B [512 n][256 k] fp16. BM=128, full K and per-ntile full-K B tile.
#define AS_STR 264
#define BS_STR 264
#define GSMEM (128 * AS_STR * 2 + 64 * BS_STR * 2 + 128 * 8 * 4)

__global__ void __launch_bounds__(256) gemm_kernel()
{
    extern __shared__ char smem[];
    half*  As   = (half*)smem;                          // [128][264]
    half*  Bs   = As + 128 * AS_STR;                    // [64][264]
    float* outs = (float*)(Bs + 64 * BS_STR);           // [128*8]

    int t = threadIdx.x;
    int warp = t >> 5, lane = t & 31;
    int gid = lane >> 2, tig = lane & 3;
    int wm = warp & 3, wn = warp >> 2;                  // 4 m-warps x 2 n-warps
    int eb = blockIdx.x * 128;

    const half* Ah = (const half*)d_AhR;
    const half* Bh = (const half*)d_BhR;

    // load full A tile (128 x 256 halves) once
    for (int c = t; c < 4096; c += 256) {
        int row = c >> 5, k8 = c & 31;
        *(float4*)&As[row * AS_STR + k8 * 8] =
            *(const float4*)&Ah[(eb + row) * 256 + k8 * 8];
    }
    for (int i = t; i < 128 * 8; i += 256) outs[i] = 0.f;

    float outp[4][8];
    #pragma unroll
    for (int i = 0; i < 4; i++)
        #pragma unroll
        for (int q = 0; q < 8; q++) outp[i][q] = 0.f;

    for (int ntile = 0; ntile < 8; ntile++) {
        __syncthreads();
        // load B tile (64 n x 256 k halves)
        for (int c = t; c < 2048; c += 256) {
            int n = c >> 5, k8 = c & 31;
            *(float4*)&Bs[n * BS_STR + k8 * 8] =
                *(const float4*)&Bh[(ntile * 64 + n) * 256 + k8 * 8];
        }
        __syncthreads();

        float acc[2][4][4];
        #pragma unroll
        for (int mt = 0; mt < 2; mt++)
            #pragma unroll
            for (int nf = 0; nf < 4; nf++)
                #pragma unroll
                for (int rr = 0; rr < 4; rr++) acc[mt][nf][rr] = 0.f;

        #pragma unroll 4
        for (int ks = 0; ks < 16; ks++) {
            int kb = ks * 16;
            u32 a[2][4];
            #pragma unroll
            for (int mt = 0; mt < 2; mt++) {
                int row = wm * 32 + mt * 16 + gid;
                a[mt][0] = *(const u32*)&As[row * AS_STR + kb + 2 * tig];
                a[mt][1] = *(const u32*)&As[(row + 8) * AS_STR + kb + 2 * tig];
                a[mt][2] = *(const u32*)&As[row * AS_STR + kb + 2 * tig + 8];
                a[mt][3] = *(const u32*)&As[(row + 8) * AS_STR + kb + 2 * tig + 8];
            }
            u32 b[4][2];
            #pragma unroll
            for (int nf = 0; nf < 4; nf++) {
                int col = wn * 32 + nf * 8 + gid;
                b[nf][0] = *(const u32*)&Bs[col * BS_STR + kb + 2 * tig];
                b[nf][1] = *(const u32*)&Bs[col * BS_STR + kb + 2 * tig + 8];
            }
            #pragma unroll
            for (int mt = 0; mt < 2; mt++)
                #pragma unroll
                for (int nf = 0; nf < 4; nf++) {
                    asm volatile(
                        "mma.sync.aligned.m16n8k16.row.col.f32.f16.f16.f32 "
                        "{%0,%1,%2,%3}, {%4,%5,%6,%7}, {%8,%9}, {%0,%1,%2,%3};"
                        : "+f"(acc[mt][nf][0]), "+f"(acc[mt][nf][1]),
                          "+f"(acc[mt][nf][2]), "+f"(acc[mt][nf][3])
                        : "r"(a[mt][0]), "r"(a[mt][1]), "r"(a[mt][2]), "r"(a[mt][3]),
                          "r"(b[nf][0]), "r"(b[nf][1]));
                }
        }

        // epilogue: cols (2j, 2j+1) = (Re, Im) live in (c0,c1) / (c2,c3)
        #pragma unroll
        for (int mt = 0; mt < 2; mt++)
            #pragma unroll
            for (int nf = 0; nf < 4; nf++) {
                int j = ntile * 32 + wn * 16 + nf * 4 + tig;
                u8 sb = SIGC.v[j];
                float p0 = acc[mt][nf][0] * acc[mt][nf][0] + acc[mt][nf][1] * acc[mt][nf][1];
                float p1 = acc[mt][nf][2] * acc[mt][nf][2] + acc[mt][nf][3] * acc[mt][nf][3];
                #pragma unroll
                for (int q = 0; q < 8; q++) {
                    float s0 = ((sb >> q) & 1) ? -p0 : p0;
                    float s1 = ((sb >> q) & 1) ? -p1 : p1;
                    outp[mt * 2 + 0][q] += s0;
                    outp[mt * 2 + 1][q] += s1;
                }
            }
    }

    #pragma unroll
    for (int idx = 0; idx < 4; idx++) {
        int row = wm * 32 + idx * 8 + gid;
        #pragma unroll
        for (int q = 0; q < 8; q++)
            atomicAdd(&outs[row * 8 + q], outp[idx][q]);
    }
    __syncthreads();
    {
        float4 v = *(float4*)&outs[t * 4];
        ((float4*)d_qout)[eb * 2 + t] = v;
    }
}

// ================= tail MLP: qout[B,8] -> out[B,1] =================
__global__ void __launch_bounds__(256) tail_kernel(const float* __restrict__ W5, const float* __restrict__ b5,
                                                   const float* __restrict__ W6, const float* __restrict__ b6,
                                                   float* __restrict__ out)
{
    __shared__ float w4s[32 * 8], b4s[32], w5s[16 * 32], b5s[16], w6s[16], b6s;
    int t = threadIdx.x;  // 256
    w4s[t] = d_W4f[t];
    if (t < 32) b4s[t] = d_b4f[t];
    for (int i = t; i < 16 * 32; i += 256) w5s[i] = W5[i];
    if (t < 16) { b5s[t] = b5[t]; w6s[t] = W6[t]; }
    if (t == 0) b6s = b6[0];
    __syncthreads();

    int e = blockIdx.x * 256 + t;
    float4 qa = *(const float4*)&d_qout[e * 8];
    float4 qb = *(const float4*)&d_qout[e * 8 + 4];
    float q[8] = {qa.x, qa.y, qa.z, qa.w, qb.x, qb.y, qb.z, qb.w};

    float h5[16];
    #pragma unroll
    for (int j = 0; j < 16; j++) h5[j] = b5s[j];
    #pragma unroll
    for (int o = 0; o < 32; o++) {
        float a = b4s[o];
        #pragma unroll
        for (int k = 0; k < 8; k++) a += w4s[o * 8 + k] * q[k];
        a = fmaxf(a, 0.f);
        #pragma unroll
        for (int j = 0; j < 16; j++) h5[j] += w5s[j * 32 + o] * a;
    }
    float o6 = b6s;
    #pragma unroll
    for (int j = 0; j < 16; j++) o6 += fmaxf(h5[j], 0.f) * w6s[j];
    out[e] = o6;
}

// ================= launch =================
extern "C" void kernel_launch(void* const* d_in, const int* in_sizes, int n_in,
                              void* d_out, int out_size)
{
    const float* x   = (const float*)d_in[0];
    const float* W1  = (const float*)d_in[1];
    const float* b1  = (const float*)d_in[2];
    const float* g1  = (const float*)d_in[3];
    const float* bt1 = (const float*)d_in[4];
    const float* m1  = (const float*)d_in[5];
    const float* v1  = (const float*)d_in[6];
    const float* W2  = (const float*)d_in[7];
    const float* b2  = (const float*)d_in[8];
    const float* g2  = (const float*)d_in[9];
    const float* bt2 = (const float*)d_in[10];
    const float* m2  = (const float*)d_in[11];
    const float* v2  = (const float*)d_in[12];
    const float* W3  = (const float*)d_in[13];
    const float* b3  = (const float*)d_in[14];
    const float* qw  = (const float*)d_in[15];
    const float* W4  = (const float*)d_in[16];
    const float* b4  = (const float*)d_in[17];
    const float* g4  = (const float*)d_in[18];
    const float* bt4 = (const float*)d_in[19];
    const float* m4  = (const float*)d_in[20];
    const float* v4_ = (const float*)d_in[21];
    const float* W5  = (const float*)d_in[22];
    const float* b5  = (const float*)d_in[23];
    const float* W6  = (const float*)d_in[24];
    const float* b6  = (const float*)d_in[25];

    static bool attr_set = false;
    if (!attr_set) {
        cudaFuncSetAttribute(gemm_kernel, cudaFuncAttributeMaxDynamicSharedMemorySize, GSMEM);
        attr_set = true;
    }

    precompute_kernel<<<1, 128>>>(W1, b1, g1, bt1, m1, v1,
                                  W2, b2, g2, bt2, m2, v2,
                                  W4, b4, g4, bt4, m4, v4_, qw);
    build_U_kernel<<<32, 256>>>();
    front_kernel<<<FB, 128>>>(x, W3, b3);
    abuild_kernel<<<BATCH / 16, 256>>>();
    gemm_kernel<<<BATCH / 128, 256, GSMEM>>>();
    tail_kernel<<<BATCH / 256, 256>>>(W5, b5, W6, b6, (float*)d_out);
}

// round 12
// speedup vs baseline: 1.3894x; 1.0682x over previous
#include <cuda_runtime.h>
#include <cuda_fp16.h>
#include <math.h>

#define BATCH 65536
#define NQ 8
#define FULLM 0xffffffffu

typedef unsigned char u8;
typedef unsigned int u32;
typedef unsigned long long ull;

// ================= compile-time GF(2) algebra for CNOT ladder =================
struct M8 { u8 c[8]; };

__host__ __device__ constexpr u8 mv(const M8& m, u8 x) {
    u8 y = 0;
    for (int j = 0; j < 8; j++) if ((x >> j) & 1) y = (u8)(y ^ m.c[j]);
    return y;
}
__host__ __device__ constexpr M8 mm(const M8& a, const M8& b) {
    M8 r{}; for (int j = 0; j < 8; j++) r.c[j] = mv(a, b.c[j]); return r;
}
__host__ __device__ constexpr M8 ident() {
    M8 m{}; for (int j = 0; j < 8; j++) m.c[j] = (u8)(1u << j); return m;
}
__host__ __device__ constexpr M8 ladder() {
    M8 L = ident();
    for (int i = 0; i < 8; i++)
        for (int j = i + 1; j < 8; j++) {
            int cb = 7 - i, tb = 7 - j;
            M8 P = ident();
            P.c[cb] = (u8)((1u << cb) | (1u << tb));
            L = mm(L, P);
        }
    return L;
}
__host__ __device__ constexpr M8 minv(const M8& a) {
    u8 row[8] = {}, inv[8] = {};
    for (int i = 0; i < 8; i++) inv[i] = (u8)(1u << i);
    for (int i = 0; i < 8; i++)
        for (int j = 0; j < 8; j++)
            if ((a.c[j] >> i) & 1) row[i] = (u8)(row[i] | (1u << j));
    for (int col = 0; col < 8; col++) {
        int piv = col;
        while (!((row[piv] >> col) & 1)) piv++;
        u8 t = row[col]; row[col] = row[piv]; row[piv] = t;
        t = inv[col]; inv[col] = inv[piv]; inv[piv] = t;
        for (int i = 0; i < 8; i++)
            if (i != col && ((row[i] >> col) & 1)) { row[i] = (u8)(row[i] ^ row[col]); inv[i] = (u8)(inv[i] ^ inv[col]); }
    }
    M8 r{};
    for (int i = 0; i < 8; i++)
        for (int j = 0; j < 8; j++)
            if ((inv[i] >> j) & 1) r.c[j] = (u8)(r.c[j] | (1u << i));
    return r;
}
__host__ __device__ constexpr int par8(int x) { x ^= x >> 4; x ^= x >> 2; x ^= x >> 1; return x & 1; }

struct Masks {
    u8 v[3][8];
    u8 r[3][8];
    u8 rf[8];
};
__host__ __device__ constexpr Masks make_masks() {
    Masks mk{};
    M8 L = ladder();
    M8 C = ident();
    for (int l = 0; l < 3; l++) {
        M8 Ci = minv(C);
        for (int q = 0; q < 8; q++) {
            int B = 7 - q;
            mk.v[l][q] = mv(C, (u8)(1u << B));
            u8 rr = 0;
            for (int j = 0; j < 8; j++) if ((Ci.c[j] >> B) & 1) rr = (u8)(rr | (1u << j));
            mk.r[l][q] = rr;
        }
        C = mm(C, L);
    }
    M8 Cf = minv(C);
    for (int q = 0; q < 8; q++) {
        int B = 7 - q;
        u8 rr = 0;
        for (int j = 0; j < 8; j++) if ((Cf.c[j] >> B) & 1) rr = (u8)(rr | (1u << j));
        mk.rf[q] = rr;
    }
    return mk;
}
constexpr Masks MK = make_masks();

__host__ __device__ constexpr bool masks_ok() {
    constexpr Masks mk = make_masks();
    M8 L = ladder();
    M8 C = ident();
    for (int l = 0; l < 3; l++) {
        M8 Ci = minv(C);
        M8 P = mm(C, Ci);
        for (int j = 0; j < 8; j++) if (P.c[j] != (u8)(1u << j)) return false;
        for (int q = 0; q < 8; q++)
            if (par8(mk.v[l][q] & mk.r[l][q]) != 1) return false;
        C = mm(C, L);
    }
    return true;
}
static_assert(masks_ok(), "GF(2) mask algebra broken");

// sign LUT: SIG.v[j] bit q = parity(j & rf[q])
struct SigT { u8 v[256]; };
__host__ __device__ constexpr SigT make_sig() {
    SigT s{};
    Masks mk = make_masks();
    for (int j = 0; j < 256; j++) {
        u8 b = 0;
        for (int q = 0; q < 8; q++) if (par8(j & mk.rf[q])) b = (u8)(b | (1u << q));
        s.v[j] = b;
    }
    return s;
}
__constant__ SigT SIGC = make_sig();

// ================= f32x2 helpers =================
__device__ __forceinline__ ull fpk(float lo, float hi) {
    ull r; asm("mov.b64 %0, {%1,%2};" : "=l"(r) : "f"(lo), "f"(hi)); return r;
}
__device__ __forceinline__ void funpk(ull v, float& lo, float& hi) {
    asm("mov.b64 {%0,%1}, %2;" : "=f"(lo), "=f"(hi) : "l"(v));
}
__device__ __forceinline__ ull mul2(ull a, ull b) {
    ull d; asm("mul.rn.f32x2 %0, %1, %2;" : "=l"(d) : "l"(a), "l"(b)); return d;
}
__device__ __forceinline__ ull fma2(ull a, ull b, ull c) {
    ull d; asm("fma.rn.f32x2 %0, %1, %2, %3;" : "=l"(d) : "l"(a), "l"(b), "l"(c)); return d;
}

struct GatePack { ull AR, AIp, AIn, BRp, BRn, BIp, BIn, pad; };

// ================= device scratch =================
__device__ float    d_W1f[128 * 16];
__device__ float    d_b1f[128];
__device__ float4   d_W2f4[64 * 32];
__device__ float    d_b2f[64];
__device__ float    d_W4f[32 * 8];
__device__ float    d_b4f[32];
__device__ GatePack d_qgp[24];
__device__ float2   d_cs[BATCH * NQ];               // (cos th/2, sin th/2)
__device__ uint4    d_BhR[512 * 32];                // B fp16 [512 n][256 k] (256KB)

// ================= precompute =================
__global__ void precompute_kernel(
    const float* W1, const float* b1, const float* g1, const float* bt1, const float* m1, const float* v1,
    const float* W2, const float* b2, const float* g2, const float* bt2, const float* m2, const float* v2,
    const float* W4, const float* b4, const float* g4, const float* bt4, const float* m4, const float* v4,
    const float* qw)
{
    int t = threadIdx.x;  // 128
    if (t < 128) {
        float a = g1[t] * rsqrtf(v1[t] + 1e-5f);
        for (int k = 0; k < 16; k++) d_W1f[t * 16 + k] = W1[t * 16 + k] * a;
        d_b1f[t] = (b1[t] - m1[t]) * a + bt1[t];
    }
    if (t < 64) {
        float a = g2[t] * rsqrtf(v2[t] + 1e-5f);
        float* w2 = (float*)d_W2f4;
        for (int k = 0; k < 128; k++) w2[t * 128 + k] = W2[t * 128 + k] * a;
        d_b2f[t] = (b2[t] - m2[t]) * a + bt2[t];
    }
    if (t < 32) {
        float a = g4[t] * rsqrtf(v4[t] + 1e-5f);
        for (int k = 0; k < 8; k++) d_W4f[t * 8 + k] = W4[t * 8 + k] * a;
        d_b4f[t] = (b4[t] - m4[t]) * a + bt4[t];
    }
    if (t < 24) {
        float sx, cx, sy, cy, sz, cz;
        sincosf(0.5f * qw[t * 3 + 0], &sx, &cx);
        sincosf(0.5f * qw[t * 3 + 1], &sy, &cy);
        sincosf(0.5f * qw[t * 3 + 2], &sz, &cz);
        float cycx = cy * cx, sysx = sy * sx, sycx = sy * cx, cysx = cy * sx;
        float ar  = cz * cycx - sz * sysx;
        float ai0 = -(cz * sysx + sz * cycx);
        float br0 = cz * sycx - sz * cysx;
        float bi  = -(cz * cysx + sz * sycx);
        Masks mk = make_masks();
        int l = t >> 3, q = t & 7;
        int rr = mk.r[l][q] & 7;
        float tau = (rr & 1) ? -1.f : 1.f;
        GatePack g;
        g.AR  = fpk(ar, ar);
        g.AIp = fpk(ai0,  tau * ai0);
        g.AIn = fpk(-ai0, -tau * ai0);
        g.BRp = fpk(br0,  tau * br0);
        g.BRn = fpk(-br0, -tau * br0);
        g.BIp = fpk(bi, bi);
        g.BIn = fpk(-bi, -bi);
        g.pad = 0;
        d_qgp[t] = g;
    }
}

// ================= packed gate machinery (verified) =================
template<int X> struct Par {
    static constexpr int val =
        ((X >> 7) ^ (X >> 6) ^ (X >> 5) ^ (X >> 4) ^ (X >> 3) ^ (X >> 2) ^ (X >> 1) ^ X) & 1;
};

template<int V, int R>
__device__ __forceinline__ void gate2(ull X[4], ull Y[4], const GatePack* gp, int lane)
{
    static_assert(Par<V & R>::val == 1, "pair/branch masks inconsistent");
    constexpr int vl = (V >> 3) & 31, vr = V & 7;
    constexpr int rl = (R >> 3) & 31, rr = R & 7;

    ull AR  = gp->AR;
    ull BIp = gp->BIp;
    ull BIn = gp->BIn;
    bool lp = (__popc(lane & rl) & 1) != 0;
    ull AIpf = lp ? gp->AIn : gp->AIp;
    ull AInf = lp ? gp->AIp : gp->AIn;
    ull BRpf = lp ? gp->BRn : gp->BRp;
    ull BRnf = lp ? gp->BRp : gp->BRn;

    ull PX[4], PY[4];
    #pragma unroll
    for (int k = 0; k < 4; k++) {
        const int kp = k ^ (vr >> 1);
        if constexpr ((vr & 1) != 0) {
            float xlo, xhi, ylo, yhi;
            funpk(X[kp], xlo, xhi);
            funpk(Y[kp], ylo, yhi);
            if constexpr (vl != 0) {
                xlo = __shfl_xor_sync(FULLM, xlo, vl);
                xhi = __shfl_xor_sync(FULLM, xhi, vl);
                ylo = __shfl_xor_sync(FULLM, ylo, vl);
                yhi = __shfl_xor_sync(FULLM, yhi, vl);
            }
            PX[k] = fpk(xhi, xlo);
            PY[k] = fpk(yhi, ylo);
        } else {
            if constexpr (vl != 0) {
                PX[k] = __shfl_xor_sync(FULLM, X[kp], vl);
                PY[k] = __shfl_xor_sync(FULLM, Y[kp], vl);
            } else {
                PX[k] = X[kp];
                PY[k] = Y[kp];
            }
        }
    }
    #pragma unroll
    for (int k = 0; k < 4; k++) {
        const bool s0 = ((__popc((2 * k) & rr) & 1) != 0);
        ull AIx = s0 ? AIpf : AInf;
        ull AIy = s0 ? AInf : AIpf;
        ull BR  = s0 ? BRnf : BRpf;
        ull t1 = mul2(X[k], AR);
        t1 = fma2(Y[k],  AIx, t1);
        t1 = fma2(PX[k], BR,  t1);
        t1 = fma2(PY[k], BIn, t1);
        ull t2 = mul2(Y[k], AR);
        t2 = fma2(X[k],  AIy, t2);
        t2 = fma2(PY[k], BR,  t2);
        t2 = fma2(PX[k], BIp, t2);
        X[k] = t1; Y[k] = t2;
    }
}

template<int L, int Q>
__device__ __forceinline__ void gate(ull X[4], ull Y[4], const GatePack* gs, int lane)
{
    gate2<MK.v[L][Q], MK.r[L][Q]>(X, Y, gs + (L * 8 + Q), lane);
}

// ================= build U: warp k simulates basis k; B stored [n=512][k=256] fp16 =================
__global__ void __launch_bounds__(256) build_U_kernel()
{
    __shared__ GatePack gs[24];
    __shared__ half Bst[512][8];
    int t = threadIdx.x;
    if (t < 192) ((ull*)gs)[t] = ((const ull*)d_qgp)[t];
    __syncthreads();

    int w = t >> 5;
    int k = blockIdx.x * 8 + w;
    int lane = t & 31;

    ull X[4], Y[4];
    #pragma unroll
    for (int p = 0; p < 4; p++) {
        int j0 = lane * 8 + 2 * p, j1 = j0 + 1;
        X[p] = fpk(j0 == k ? 1.f : 0.f, j1 == k ? 1.f : 0.f);
        Y[p] = fpk(0.f, 0.f);
    }

    gate<0,0>(X, Y, gs, lane); gate<0,1>(X, Y, gs, lane); gate<0,2>(X, Y, gs, lane); gate<0,3>(X, Y, gs, lane);
    gate<0,4>(X, Y, gs, lane); gate<0,5>(X, Y, gs, lane); gate<0,6>(X, Y, gs, lane); gate<0,7>(X, Y, gs, lane);
    gate<1,0>(X, Y, gs, lane); gate<1,1>(X, Y, gs, lane); gate<1,2>(X, Y, gs, lane); gate<1,3>(X, Y, gs, lane);
    gate<1,4>(X, Y, gs, lane); gate<1,5>(X, Y, gs, lane); gate<1,6>(X, Y, gs, lane); gate<1,7>(X, Y, gs, lane);
    gate<2,0>(X, Y, gs, lane); gate<2,1>(X, Y, gs, lane); gate<2,2>(X, Y, gs, lane); gate<2,3>(X, Y, gs, lane);
    gate<2,4>(X, Y, gs, lane); gate<2,5>(X, Y, gs, lane); gate<2,6>(X, Y, gs, lane); gate<2,7>(X, Y, gs, lane);

    #pragma unroll
    for (int p = 0; p < 4; p++) {
        float x0, x1, y0, y1;
        funpk(X[p], x0, x1);
        funpk(Y[p], y0, y1);
        int j0 = lane * 8 + 2 * p, j1 = j0 + 1;
        Bst[2 * j0][w]     = __float2half_rn(x0);
        Bst[2 * j0 + 1][w] = __float2half_rn(y0);
        Bst[2 * j1][w]     = __float2half_rn(x1);
        Bst[2 * j1 + 1][w] = __float2half_rn(y1);
    }
    __syncthreads();

    half* Bh = (half*)d_BhR;
    for (int i = t; i < 512; i += 256)
        *(uint4*)&Bh[i * 256 + blockIdx.x * 8] = *(uint4*)&Bst[i][0];
}

// ================= front MLP: x[B,16] -> cs pairs =================
#define FB 2048
#define FROWS 32
#define FTILE 16

__global__ void __launch_bounds__(128) front_kernel(const float* __restrict__ x,
                                                    const float* __restrict__ W3,
                                                    const float* __restrict__ b3)
{
    __shared__ float4 w2s4[64 * 32];
    __shared__ float4 w3s4[8 * 16];
    __shared__ float4 xs4[FTILE][4];
    __shared__ float4 h1s4[FTILE][32];
    __shared__ float4 h2s4[FTILE][16];
    __shared__ float  b2s[64], b3s[8];

    int t = threadIdx.x;  // 128
    for (int i = t; i < 64 * 32; i += 128) {
        int o = i >> 5, k = i & 31;
        w2s4[(o << 5) + (k ^ (o & 7))] = d_W2f4[i];
    }
    {
        const float4* W34 = (const float4*)W3;
        if (t < 8 * 16) w3s4[t] = W34[t];
        if (t < 64) b2s[t] = d_b2f[t];
        if (t < 8)  b3s[t] = b3[t];
    }
    float w1[16];
    #pragma unroll
    for (int k = 0; k < 16; k++) w1[k] = d_W1f[t * 16 + k];
    float bb1 = d_b1f[t];
    __syncthreads();

    const float4* x4 = (const float4*)x;
    int base = blockIdx.x * FROWS;

    for (int it = 0; it < FROWS / FTILE; it++) {
        int rbase = base + it * FTILE;
        if (t < FTILE * 4) xs4[t >> 2][t & 3] = x4[(rbase + (t >> 2)) * 4 + (t & 3)];
        __syncthreads();

        #pragma unroll
        for (int r = 0; r < FTILE; r++) {
            float4 xa = xs4[r][0], xb = xs4[r][1], xc = xs4[r][2], xd = xs4[r][3];
            float a = bb1;
            a += w1[0]*xa.x + w1[1]*xa.y + w1[2]*xa.z + w1[3]*xa.w;
            a += w1[4]*xb.x + w1[5]*xb.y + w1[6]*xb.z + w1[7]*xb.w;
            a += w1[8]*xc.x + w1[9]*xc.y + w1[10]*xc.z + w1[11]*xc.w;
            a += w1[12]*xd.x + w1[13]*xd.y + w1[14]*xd.z + w1[15]*xd.w;
            ((float*)&h1s4[r][0])[t] = fmaxf(a, 0.f);
        }
        __syncthreads();

        {
            int o = t & 63, half_ = t >> 6;
            int obase = o << 5, osw = o & 7;
            float acc[8];
            #pragma unroll
            for (int rr = 0; rr < 8; rr++) acc[rr] = b2s[o];
            #pragma unroll 4
            for (int k4 = 0; k4 < 32; k4++) {
                float4 w = w2s4[obase + (k4 ^ osw)];
                #pragma unroll
                for (int rr = 0; rr < 8; rr++) {
                    float4 h = h1s4[half_ * 8 + rr][k4];
                    acc[rr] += w.x*h.x + w.y*h.y + w.z*h.z + w.w*h.w;
                }
            }
            #pragma unroll
            for (int rr = 0; rr < 8; rr++)
                ((float*)&h2s4[half_ * 8 + rr][0])[o] = fmaxf(acc[rr], 0.f);
        }
        __syncthreads();

        {
            int r = t >> 3, o = t & 7;
            float a = b3s[o];
            #pragma unroll
            for (int k4 = 0; k4 < 16; k4++) {
                float4 w = w3s4[o * 16 + k4];
                float4 h = h2s4[r][k4];
                a += w.x*h.x + w.y*h.y + w.z*h.z + w.w*h.w;
            }
            float pre = tanhf(a);
            float sc, cc;
            __sincosf(0.5f * pre, &sc, &cc);
            d_cs[(rbase + r) * 8 + o] = make_float2(cc, sc);
        }
        __syncthreads();
    }
}

// ================= fused GEMM: A built in-smem, S=A*B, |.|^2, parity, tail MLP =================
// A[e][i] = prod_q (bit(i,7-q) ? -s_q : c_q), fp16 in smem. B [512 n][256 k] fp16 global.
// BM=128, 8 warps (4 m x 2 n), warp tile 32x32, whole K resident.
#define AS_STR 264
#define BS_STR 264
#define GSMEM (128 * AS_STR * 2 + 64 * BS_STR * 2 + 128 * 8 * 4)

__global__ void __launch_bounds__(256, 2) gemm_kernel(
    const float* __restrict__ W5, const float* __restrict__ b5,
    const float* __restrict__ W6, const float* __restrict__ b6,
    float* __restrict__ out)
{
    extern __shared__ char smem[];
    half*  As   = (half*)smem;                          // [128][264]
    half*  Bs   = As + 128 * AS_STR;                    // [64][264]
    float* outs = (float*)(Bs + 64 * BS_STR);           // [128*8]
    __shared__ float w4s[32 * 8], b4s[32], w5s[16 * 32], b5s[16], w6s[16], b6s[1];

    int t = threadIdx.x;
    int warp = t >> 5, lane = t & 31;
    int gid = lane >> 2, tig = lane & 3;
    int wm = warp & 3, wn = warp >> 2;
    int eb = blockIdx.x * 128;

    const half* Bh = (const half*)d_BhR;

    // ---- stage tail weights ----
    w4s[t] = d_W4f[t];
    if (t < 32) b4s[t] = d_b4f[t];
    for (int i = t; i < 16 * 32; i += 256) w5s[i] = W5[i];
    if (t < 16) { b5s[t] = b5[t]; w6s[t] = W6[t]; }
    if (t == 0) b6s[0] = b6[0];

    // ---- build A tile in smem: thread (rrow = t>>1, h = t&1) builds 8x16 halves ----
    {
        int rrow = t >> 1, h = t & 1;
        float2 cs[8];
        #pragma unroll
        for (int q = 0; q < 8; q++) cs[q] = d_cs[(eb + rrow) * 8 + q];
        #pragma unroll
        for (int hi8 = 0; hi8 < 8; hi8++) {
            int hi = h * 8 + hi8;   // k bits 7..4
            float fhi = 1.f;
            fhi *= (hi & 8) ? -cs[0].y : cs[0].x;
            fhi *= (hi & 4) ? -cs[1].y : cs[1].x;
            fhi *= (hi & 2) ? -cs[2].y : cs[2].x;
            fhi *= (hi & 1) ? -cs[3].y : cs[3].x;
            float A1[2], A2[4], A3[8], A4[16];
            A1[0] = fhi * cs[4].x;  A1[1] = -fhi * cs[4].y;
            #pragma unroll
            for (int i = 0; i < 4; i++)  A2[i] = A1[i >> 1] * ((i & 1) ? -cs[5].y : cs[5].x);
            #pragma unroll
            for (int i = 0; i < 8; i++)  A3[i] = A2[i >> 1] * ((i & 1) ? -cs[6].y : cs[6].x);
            #pragma unroll
            for (int i = 0; i < 16; i++) A4[i] = A3[i >> 1] * ((i & 1) ? -cs[7].y : cs[7].x);
            half2 h2v[8];
            #pragma unroll
            for (int i = 0; i < 8; i++) h2v[i] = __floats2half2_rn(A4[2 * i], A4[2 * i + 1]);
            uint4* dst = (uint4*)&As[rrow * AS_STR + hi * 16];
            dst[0] = *(uint4*)&h2v[0];
            dst[1] = *(uint4*)&h2v[4];
        }
    }
    for (int i = t; i < 128 * 8; i += 256) outs[i] = 0.f;

    float outp[4][8];
    #pragma unroll
    for (int i = 0; i < 4; i++)
        #pragma unroll
        for (int q = 0; q < 8; q++) outp[i][q] = 0.f;

    for (int ntile = 0; ntile < 8; ntile++) {
        __syncthreads();
        for (int c = t; c < 2048; c += 256) {
            int n = c >> 5, k8 = c & 31;
            *(float4*)&Bs[n * BS_STR + k8 * 8] =
                *(const float4*)&Bh[(ntile * 64 + n) * 256 + k8 * 8];
        }
        __syncthreads();

        float acc[2][4][4];
        #pragma unroll
        for (int mt = 0; mt < 2; mt++)
            #pragma unroll
            for (int nf = 0; nf < 4; nf++)
                #pragma unroll
                for (int rr = 0; rr < 4; rr++) acc[mt][nf][rr] = 0.f;

        #pragma unroll 4
        for (int ks = 0; ks < 16; ks++) {
            int kb = ks * 16;
            u32 a[2][4];
            #pragma unroll
            for (int mt = 0; mt < 2; mt++) {
                int row = wm * 32 + mt * 16 + gid;
                a[mt][0] = *(const u32*)&As[row * AS_STR + kb + 2 * tig];
                a[mt][1] = *(const u32*)&As[(row + 8) * AS_STR + kb + 2 * tig];
                a[mt][2] = *(const u32*)&As[row * AS_STR + kb + 2 * tig + 8];
                a[mt][3] = *(const u32*)&As[(row + 8) * AS_STR + kb + 2 * tig + 8];
            }
            u32 b[4][2];
            #pragma unroll
            for (int nf = 0; nf < 4; nf++) {
                int col = wn * 32 + nf * 8 + gid;
                b[nf][0] = *(const u32*)&Bs[col * BS_STR + kb + 2 * tig];
                b[nf][1] = *(const u32*)&Bs[col * BS_STR + kb + 2 * tig + 8];
            }
            #pragma unroll
            for (int mt = 0; mt < 2; mt++)
                #pragma unroll
                for (int nf = 0; nf < 4; nf++) {
                    asm volatile(
                        "mma.sync.aligned.m16n8k16.row.col.f32.f16.f16.f32 "
                        "{%0,%1,%2,%3}, {%4,%5,%6,%7}, {%8,%9}, {%0,%1,%2,%3};"
                        : "+f"(acc[mt][nf][0]), "+f"(acc[mt][nf][1]),
                          "+f"(acc[mt][nf][2]), "+f"(acc[mt][nf][3])
                        : "r"(a[mt][0]), "r"(a[mt][1]), "r"(a[mt][2]), "r"(a[mt][3]),
                          "r"(b[nf][0]), "r"(b[nf][1]));
                }
        }

        // epilogue: cols (2j, 2j+1) = (Re, Im) in (c0,c1)/(c2,c3)
        #pragma unroll
        for (int mt = 0; mt < 2; mt++)
            #pragma unroll
            for (int nf = 0; nf < 4; nf++) {
                int j = ntile * 32 + wn * 16 + nf * 4 + tig;
                u8 sb = SIGC.v[j];
                float p0 = acc[mt][nf][0] * acc[mt][nf][0] + acc[mt][nf][1] * acc[mt][nf][1];
                float p1 = acc[mt][nf][2] * acc[mt][nf][2] + acc[mt][nf][3] * acc[mt][nf][3];
                #pragma unroll
                for (int q = 0; q < 8; q++) {
                    float s0 = ((sb >> q) & 1) ? -p0 : p0;
                    float s1 = ((sb >> q) & 1) ? -p1 : p1;
                    outp[mt * 2 + 0][q] += s0;
                    outp[mt * 2 + 1][q] += s1;
                }
            }
    }

    #pragma unroll
    for (int idx = 0; idx < 4; idx++) {
        int row = wm * 32 + idx * 8 + gid;
        #pragma unroll
        for (int q = 0; q < 8; q++)
            atomicAdd(&outs[row * 8 + q], outp[idx][q]);
    }
    __syncthreads();

    // ---- fused tail MLP: one thread per row ----
    if (t < 128) {
        float q[8];
        #pragma unroll
        for (int i = 0; i < 8; i++) q[i] = outs[t * 8 + i];

        float h5[16];
        #pragma unroll
        for (int j = 0; j < 16; j++) h5[j] = b5s[j];
        #pragma unroll
        for (int o = 0; o < 32; o++) {
            float a = b4s[o];
            #pragma unroll
            for (int k = 0; k < 8; k++) a += w4s[o * 8 + k] * q[k];
            a = fmaxf(a, 0.f);
            #pragma unroll
            for (int j = 0; j < 16; j++) h5[j] += w5s[j * 32 + o] * a;
        }
        float o6 = b6s[0];
        #pragma unroll
        for (int j = 0; j < 16; j++) o6 += fmaxf(h5[j], 0.f) * w6s[j];
        out[eb + t] = o6;
    }
}

// ================= launch =================
extern "C" void kernel_launch(void* const* d_in, const int* in_sizes, int n_in,
                              void* d_out, int out_size)
{
    const float* x   = (const float*)d_in[0];
    const float* W1  = (const float*)d_in[1];
    const float* b1  = (const float*)d_in[2];
    const float* g1  = (const float*)d_in[3];
    const float* bt1 = (const float*)d_in[4];
    const float* m1  = (const float*)d_in[5];
    const float* v1  = (const float*)d_in[6];
    const float* W2  = (const float*)d_in[7];
    const float* b2  = (const float*)d_in[8];
    const float* g2  = (const float*)d_in[9];
    const float* bt2 = (const float*)d_in[10];
    const float* m2  = (const float*)d_in[11];
    const float* v2  = (const float*)d_in[12];
    const float* W3  = (const float*)d_in[13];
    const float* b3  = (const float*)d_in[14];
    const float* qw  = (const float*)d_in[15];
    const float* W4  = (const float*)d_in[16];
    const float* b4  = (const float*)d_in[17];
    const float* g4  = (const float*)d_in[18];
    const float* bt4 = (const float*)d_in[19];
    const float* m4  = (const float*)d_in[20];
    const float* v4_ = (const float*)d_in[21];
    const float* W5  = (const float*)d_in[22];
    const float* b5  = (const float*)d_in[23];
    const float* W6  = (const float*)d_in[24];
    const float* b6  = (const float*)d_in[25];

    static bool attr_set = false;
    if (!attr_set) {
        cudaFuncSetAttribute(gemm_kernel, cudaFuncAttributeMaxDynamicSharedMemorySize, GSMEM);
        attr_set = true;
    }

    precompute_kernel<<<1, 128>>>(W1, b1, g1, bt1, m1, v1,
                                  W2, b2, g2, bt2, m2, v2,
                                  W4, b4, g4, bt4, m4, v4_, qw);
    build_U_kernel<<<32, 256>>>();
    front_kernel<<<FB, 128>>>(x, W3, b3);
    gemm_kernel<<<BATCH / 128, 256, GSMEM>>>(W5, b5, W6, b6, (float*)d_out);
}

// round 14
// speedup vs baseline: 1.4412x; 1.0373x over previous
#include <cuda_runtime.h>
#include <cuda_fp16.h>
#include <math.h>

#define BATCH 65536
#define NQ 8
#define FULLM 0xffffffffu

typedef unsigned char u8;
typedef unsigned int u32;
typedef unsigned long long ull;

// ================= compile-time GF(2) algebra for CNOT ladder =================
struct M8 { u8 c[8]; };

__host__ __device__ constexpr u8 mv(const M8& m, u8 x) {
    u8 y = 0;
    for (int j = 0; j < 8; j++) if ((x >> j) & 1) y = (u8)(y ^ m.c[j]);
    return y;
}
__host__ __device__ constexpr M8 mm(const M8& a, const M8& b) {
    M8 r{}; for (int j = 0; j < 8; j++) r.c[j] = mv(a, b.c[j]); return r;
}
__host__ __device__ constexpr M8 ident() {
    M8 m{}; for (int j = 0; j < 8; j++) m.c[j] = (u8)(1u << j); return m;
}
__host__ __device__ constexpr M8 ladder() {
    M8 L = ident();
    for (int i = 0; i < 8; i++)
        for (int j = i + 1; j < 8; j++) {
            int cb = 7 - i, tb = 7 - j;
            M8 P = ident();
            P.c[cb] = (u8)((1u << cb) | (1u << tb));
            L = mm(L, P);
        }
    return L;
}
__host__ __device__ constexpr M8 minv(const M8& a) {
    u8 row[8] = {}, inv[8] = {};
    for (int i = 0; i < 8; i++) inv[i] = (u8)(1u << i);
    for (int i = 0; i < 8; i++)
        for (int j = 0; j < 8; j++)
            if ((a.c[j] >> i) & 1) row[i] = (u8)(row[i] | (1u << j));
    for (int col = 0; col < 8; col++) {
        int piv = col;
        while (!((row[piv] >> col) & 1)) piv++;
        u8 t = row[col]; row[col] = row[piv]; row[piv] = t;
        t = inv[col]; inv[col] = inv[piv]; inv[piv] = t;
        for (int i = 0; i < 8; i++)
            if (i != col && ((row[i] >> col) & 1)) { row[i] = (u8)(row[i] ^ row[col]); inv[i] = (u8)(inv[i] ^ inv[col]); }
    }
    M8 r{};
    for (int i = 0; i < 8; i++)
        for (int j = 0; j < 8; j++)
            if ((inv[i] >> j) & 1) r.c[j] = (u8)(r.c[j] | (1u << i));
    return r;
}
__host__ __device__ constexpr int par8(int x) { x ^= x >> 4; x ^= x >> 2; x ^= x >> 1; return x & 1; }

struct Masks {
    u8 v[3][8];
    u8 r[3][8];
    u8 rf[8];
};
__host__ __device__ constexpr Masks make_masks() {
    Masks mk{};
    M8 L = ladder();
    M8 C = ident();
    for (int l = 0; l < 3; l++) {
        M8 Ci = minv(C);
        for (int q = 0; q < 8; q++) {
            int B = 7 - q;
            mk.v[l][q] = mv(C, (u8)(1u << B));
            u8 rr = 0;
            for (int j = 0; j < 8; j++) if ((Ci.c[j] >> B) & 1) rr = (u8)(rr | (1u << j));
            mk.r[l][q] = rr;
        }
        C = mm(C, L);
    }
    M8 Cf = minv(C);
    for (int q = 0; q < 8; q++) {
        int B = 7 - q;
        u8 rr = 0;
        for (int j = 0; j < 8; j++) if ((Cf.c[j] >> B) & 1) rr = (u8)(rr | (1u << j));
        mk.rf[q] = rr;
    }
    return mk;
}
constexpr Masks MK = make_masks();

__host__ __device__ constexpr bool masks_ok() {
    constexpr Masks mk = make_masks();
    M8 L = ladder();
    M8 C = ident();
    for (int l = 0; l < 3; l++) {
        M8 Ci = minv(C);
        M8 P = mm(C, Ci);
        for (int j = 0; j < 8; j++) if (P.c[j] != (u8)(1u << j)) return false;
        for (int q = 0; q < 8; q++)
            if (par8(mk.v[l][q] & mk.r[l][q]) != 1) return false;
        C = mm(C, L);
    }
    return true;
}
static_assert(masks_ok(), "GF(2) mask algebra broken");

// sign LUT: SIG.v[j] bit q = parity(j & rf[q])
struct SigT { u8 v[256]; };
__host__ __device__ constexpr SigT make_sig() {
    SigT s{};
    Masks mk = make_masks();
    for (int j = 0; j < 256; j++) {
        u8 b = 0;
        for (int q = 0; q < 8; q++) if (par8(j & mk.rf[q])) b = (u8)(b | (1u << q));
        s.v[j] = b;
    }
    return s;
}
__constant__ SigT SIGC = make_sig();

// ================= f32x2 / smem helpers =================
__device__ __forceinline__ ull fpk(float lo, float hi) {
    ull r; asm("mov.b64 %0, {%1,%2};" : "=l"(r) : "f"(lo), "f"(hi)); return r;
}
__device__ __forceinline__ void funpk(ull v, float& lo, float& hi) {
    asm("mov.b64 {%0,%1}, %2;" : "=f"(lo), "=f"(hi) : "l"(v));
}
__device__ __forceinline__ ull mul2(ull a, ull b) {
    ull d; asm("mul.rn.f32x2 %0, %1, %2;" : "=l"(d) : "l"(a), "l"(b)); return d;
}
__device__ __forceinline__ ull fma2(ull a, ull b, ull c) {
    ull d; asm("fma.rn.f32x2 %0, %1, %2, %3;" : "=l"(d) : "l"(a), "l"(b), "l"(c)); return d;
}
__device__ __forceinline__ void ldsm_x4(u32& r0, u32& r1, u32& r2, u32& r3, u32 addr) {
    asm volatile("ldmatrix.sync.aligned.m8n8.x4.shared.b16 {%0,%1,%2,%3}, [%4];"
                 : "=r"(r0), "=r"(r1), "=r"(r2), "=r"(r3) : "r"(addr));
}

struct GatePack { ull AR, AIp, AIn, BRp, BRn, BIp, BIn, pad; };

// ================= device scratch =================
__device__ float    d_W1f[128 * 16];
__device__ float    d_b1f[128];
__device__ float4   d_W2f4[64 * 32];
__device__ float    d_b2f[64];
__device__ float    d_W4f[32 * 8];
__device__ float    d_b4f[32];
__device__ GatePack d_qgp[24];
__device__ float2   d_cs[BATCH * NQ];               // (cos th/2, sin th/2)
__device__ uint4    d_BhR[512 * 32];                // B fp16 [512 n][256 k] (256KB)

// ================= precompute =================
__global__ void precompute_kernel(
    const float* W1, const float* b1, const float* g1, const float* bt1, const float* m1, const float* v1,
    const float* W2, const float* b2, const float* g2, const float* bt2, const float* m2, const float* v2,
    const float* W4, const float* b4, const float* g4, const float* bt4, const float* m4, const float* v4,
    const float* qw)
{
    int t = threadIdx.x;  // 128
    if (t < 128) {
        float a = g1[t] * rsqrtf(v1[t] + 1e-5f);
        for (int k = 0; k < 16; k++) d_W1f[t * 16 + k] = W1[t * 16 + k] * a;
        d_b1f[t] = (b1[t] - m1[t]) * a + bt1[t];
    }
    if (t < 64) {
        float a = g2[t] * rsqrtf(v2[t] + 1e-5f);
        float* w2 = (float*)d_W2f4;
        for (int k = 0; k < 128; k++) w2[t * 128 + k] = W2[t * 128 + k] * a;
        d_b2f[t] = (b2[t] - m2[t]) * a + bt2[t];
    }
    if (t < 32) {
        float a = g4[t] * rsqrtf(v4[t] + 1e-5f);
        for (int k = 0; k < 8; k++) d_W4f[t * 8 + k] = W4[t * 8 + k] * a;
        d_b4f[t] = (b4[t] - m4[t]) * a + bt4[t];
    }
    if (t < 24) {
        float sx, cx, sy, cy, sz, cz;
        sincosf(0.5f * qw[t * 3 + 0], &sx, &cx);
        sincosf(0.5f * qw[t * 3 + 1], &sy, &cy);
        sincosf(0.5f * qw[t * 3 + 2], &sz, &cz);
        float cycx = cy * cx, sysx = sy * sx, sycx = sy * cx, cysx = cy * sx;
        float ar  = cz * cycx - sz * sysx;
        float ai0 = -(cz * sysx + sz * cycx);
        float br0 = cz * sycx - sz * cysx;
        float bi  = -(cz * cysx + sz * sycx);
        Masks mk = make_masks();
        int l = t >> 3, q = t & 7;
        int rr = mk.r[l][q] & 7;
        float tau = (rr & 1) ? -1.f : 1.f;
        GatePack g;
        g.AR  = fpk(ar, ar);
        g.AIp = fpk(ai0,  tau * ai0);
        g.AIn = fpk(-ai0, -tau * ai0);
        g.BRp = fpk(br0,  tau * br0);
        g.BRn = fpk(-br0, -tau * br0);
        g.BIp = fpk(bi, bi);
        g.BIn = fpk(-bi, -bi);
        g.pad = 0;
        d_qgp[t] = g;
    }
}

// ================= packed gate machinery (verified) =================
template<int X> struct Par {
    static constexpr int val =
        ((X >> 7) ^ (X >> 6) ^ (X >> 5) ^ (X >> 4) ^ (X >> 3) ^ (X >> 2) ^ (X >> 1) ^ X) & 1;
};

template<int V, int R>
__device__ __forceinline__ void gate2(ull X[4], ull Y[4], const GatePack* gp, int lane)
{
    static_assert(Par<V & R>::val == 1, "pair/branch masks inconsistent");
    constexpr int vl = (V >> 3) & 31, vr = V & 7;
    constexpr int rl = (R >> 3) & 31, rr = R & 7;

    ull AR  = gp->AR;
    ull BIp = gp->BIp;
    ull BIn = gp->BIn;
    bool lp = (__popc(lane & rl) & 1) != 0;
    ull AIpf = lp ? gp->AIn : gp->AIp;
    ull AInf = lp ? gp->AIp : gp->AIn;
    ull BRpf = lp ? gp->BRn : gp->BRp;
    ull BRnf = lp ? gp->BRp : gp->BRn;

    ull PX[4], PY[4];
    #pragma unroll
    for (int k = 0; k < 4; k++) {
        const int kp = k ^ (vr >> 1);
        if constexpr ((vr & 1) != 0) {
            float xlo, xhi, ylo, yhi;
            funpk(X[kp], xlo, xhi);
            funpk(Y[kp], ylo, yhi);
            if constexpr (vl != 0) {
                xlo = __shfl_xor_sync(FULLM, xlo, vl);
                xhi = __shfl_xor_sync(FULLM, xhi, vl);
                ylo = __shfl_xor_sync(FULLM, ylo, vl);
                yhi = __shfl_xor_sync(FULLM, yhi, vl);
            }
            PX[k] = fpk(xhi, xlo);
            PY[k] = fpk(yhi, ylo);
        } else {
            if constexpr (vl != 0) {
                PX[k] = __shfl_xor_sync(FULLM, X[kp], vl);
                PY[k] = __shfl_xor_sync(FULLM, Y[kp], vl);
            } else {
                PX[k] = X[kp];
                PY[k] = Y[kp];
            }
        }
    }
    #pragma unroll
    for (int k = 0; k < 4; k++) {
        const bool s0 = ((__popc((2 * k) & rr) & 1) != 0);
        ull AIx = s0 ? AIpf : AInf;
        ull AIy = s0 ? AInf : AIpf;
        ull BR  = s0 ? BRnf : BRpf;
        ull t1 = mul2(X[k], AR);
        t1 = fma2(Y[k],  AIx, t1);
        t1 = fma2(PX[k], BR,  t1);
        t1 = fma2(PY[k], BIn, t1);
        ull t2 = mul2(Y[k], AR);
        t2 = fma2(X[k],  AIy, t2);
        t2 = fma2(PY[k], BR,  t2);
        t2 = fma2(PX[k], BIp, t2);
        X[k] = t1; Y[k] = t2;
    }
}

template<int L, int Q>
__device__ __forceinline__ void gate(ull X[4], ull Y[4], const GatePack* gs, int lane)
{
    gate2<MK.v[L][Q], MK.r[L][Q]>(X, Y, gs + (L * 8 + Q), lane);
}

// ================= build U: warp k simulates basis k; B stored [n=512][k=256] fp16 =================
__global__ void __launch_bounds__(256) build_U_kernel()
{
    __shared__ GatePack gs[24];
    __shared__ half Bst[512][8];
    int t = threadIdx.x;
    if (t < 192) ((ull*)gs)[t] = ((const ull*)d_qgp)[t];
    __syncthreads();

    int w = t >> 5;
    int k = blockIdx.x * 8 + w;
    int lane = t & 31;

    ull X[4], Y[4];
    #pragma unroll
    for (int p = 0; p < 4; p++) {
        int j0 = lane * 8 + 2 * p, j1 = j0 + 1;
        X[p] = fpk(j0 == k ? 1.f : 0.f, j1 == k ? 1.f : 0.f);
        Y[p] = fpk(0.f, 0.f);
    }

    gate<0,0>(X, Y, gs, lane); gate<0,1>(X, Y, gs, lane); gate<0,2>(X, Y, gs, lane); gate<0,3>(X, Y, gs, lane);
    gate<0,4>(X, Y, gs, lane); gate<0,5>(X, Y, gs, lane); gate<0,6>(X, Y, gs, lane); gate<0,7>(X, Y, gs, lane);
    gate<1,0>(X, Y, gs, lane); gate<1,1>(X, Y, gs, lane); gate<1,2>(X, Y, gs, lane); gate<1,3>(X, Y, gs, lane);
    gate<1,4>(X, Y, gs, lane); gate<1,5>(X, Y, gs, lane); gate<1,6>(X, Y, gs, lane); gate<1,7>(X, Y, gs, lane);
    gate<2,0>(X, Y, gs, lane); gate<2,1>(X, Y, gs, lane); gate<2,2>(X, Y, gs, lane); gate<2,3>(X, Y, gs, lane);
    gate<2,4>(X, Y, gs, lane); gate<2,5>(X, Y, gs, lane); gate<2,6>(X, Y, gs, lane); gate<2,7>(X, Y, gs, lane);

    #pragma unroll
    for (int p = 0; p < 4; p++) {
        float x0, x1, y0, y1;
        funpk(X[p], x0, x1);
        funpk(Y[p], y0, y1);
        int j0 = lane * 8 + 2 * p, j1 = j0 + 1;
        Bst[2 * j0][w]     = __float2half_rn(x0);
        Bst[2 * j0 + 1][w] = __float2half_rn(y0);
        Bst[2 * j1][w]     = __float2half_rn(x1);
        Bst[2 * j1 + 1][w] = __float2half_rn(y1);
    }
    __syncthreads();

    half* Bh = (half*)d_BhR;
    for (int i = t; i < 512; i += 256)
        *(uint4*)&Bh[i * 256 + blockIdx.x * 8] = *(uint4*)&Bst[i][0];
}

// ================= front MLP: x[B,16] -> cs pairs =================
#define FB 2048
#define FROWS 32
#define FTILE 16

__global__ void __launch_bounds__(128) front_kernel(const float* __restrict__ x,
                                                    const float* __restrict__ W3,
                                                    const float* __restrict__ b3)
{
    __shared__ float4 w2s4[64 * 32];
    __shared__ float4 w3s4[8 * 16];
    __shared__ float4 xs4[FTILE][4];
    __shared__ float4 h1s4[FTILE][32];
    __shared__ float4 h2s4[FTILE][16];
    __shared__ float  b2s[64], b3s[8];

    int t = threadIdx.x;  // 128
    for (int i = t; i < 64 * 32; i += 128) {
        int o = i >> 5, k = i & 31;
        w2s4[(o << 5) + (k ^ (o & 7))] = d_W2f4[i];
    }
    {
        const float4* W34 = (const float4*)W3;
        if (t < 8 * 16) w3s4[t] = W34[t];
        if (t < 64) b2s[t] = d_b2f[t];
        if (t < 8)  b3s[t] = b3[t];
    }
    float w1[16];
    #pragma unroll
    for (int k = 0; k < 16; k++) w1[k] = d_W1f[t * 16 + k];
    float bb1 = d_b1f[t];
    __syncthreads();

    const float4* x4 = (const float4*)x;
    int base = blockIdx.x * FROWS;

    for (int it = 0; it < FROWS / FTILE; it++) {
        int rbase = base + it * FTILE;
        if (t < FTILE * 4) xs4[t >> 2][t & 3] = x4[(rbase + (t >> 2)) * 4 + (t & 3)];
        __syncthreads();

        #pragma unroll
        for (int r = 0; r < FTILE; r++) {
            float4 xa = xs4[r][0], xb = xs4[r][1], xc = xs4[r][2], xd = xs4[r][3];
            float a = bb1;
            a += w1[0]*xa.x + w1[1]*xa.y + w1[2]*xa.z + w1[3]*xa.w;
            a += w1[4]*xb.x + w1[5]*xb.y + w1[6]*xb.z + w1[7]*xb.w;
            a += w1[8]*xc.x + w1[9]*xc.y + w1[10]*xc.z + w1[11]*xc.w;
            a += w1[12]*xd.x + w1[13]*xd.y + w1[14]*xd.z + w1[15]*xd.w;
            ((float*)&h1s4[r][0])[t] = fmaxf(a, 0.f);
        }
        __syncthreads();

        {
            int o = t & 63, half_ = t >> 6;
            int obase = o << 5, osw = o & 7;
            float acc[8];
            #pragma unroll
            for (int rr = 0; rr < 8; rr++) acc[rr] = b2s[o];
            #pragma unroll 4
            for (int k4 = 0; k4 < 32; k4++) {
                float4 w = w2s4[obase + (k4 ^ osw)];
                #pragma unroll
                for (int rr = 0; rr < 8; rr++) {
                    float4 h = h1s4[half_ * 8 + rr][k4];
                    acc[rr] += w.x*h.x + w.y*h.y + w.z*h.z + w.w*h.w;
                }
            }
            #pragma unroll
            for (int rr = 0; rr < 8; rr++)
                ((float*)&h2s4[half_ * 8 + rr][0])[o] = fmaxf(acc[rr], 0.f);
        }
        __syncthreads();

        {
            int r = t >> 3, o = t & 7;
            float a = b3s[o];
            #pragma unroll
            for (int k4 = 0; k4 < 16; k4++) {
                float4 w = w3s4[o * 16 + k4];
                float4 h = h2s4[r][k4];
                a += w.x*h.x + w.y*h.y + w.z*h.z + w.w*h.w;
            }
            float pre = tanhf(a);
            float sc, cc;
            __sincosf(0.5f * pre, &sc, &cc);
            d_cs[(rbase + r) * 8 + o] = make_float2(cc, sc);
        }
        __syncthreads();
    }
}

// ================= fused GEMM (ldmatrix fragments) =================
#define AS_STR 264
#define BS_STR 264
#define GSMEM (128 * AS_STR * 2 + 64 * BS_STR * 2 + 128 * 8 * 4)

__global__ void __launch_bounds__(256, 2) gemm_kernel(
    const float* __restrict__ W5, const float* __restrict__ b5,
    const float* __restrict__ W6, const float* __restrict__ b6,
    float* __restrict__ out)
{
    extern __shared__ char smem[];
    half*  As   = (half*)smem;                          // [128][264]
    half*  Bs   = As + 128 * AS_STR;                    // [64][264]
    float* outs = (float*)(Bs + 64 * BS_STR);           // [128*8]
    __shared__ float w4s[32 * 8], b4s[32], w5s[16 * 32], b5s[16], w6s[16], b6s[1];

    int t = threadIdx.x;
    int warp = t >> 5, lane = t & 31;
    int gid = lane >> 2, tig = lane & 3;
    int wm = warp & 3, wn = warp >> 2;
    int eb = blockIdx.x * 128;

    const half* Bh = (const half*)d_BhR;

    // ---- stage tail weights ----
    w4s[t] = d_W4f[t];
    if (t < 32) b4s[t] = d_b4f[t];
    for (int i = t; i < 16 * 32; i += 256) w5s[i] = W5[i];
    if (t < 16) { b5s[t] = b5[t]; w6s[t] = W6[t]; }
    if (t == 0) b6s[0] = b6[0];

    // ---- build A tile in smem ----
    {
        int rrow = t >> 1, h = t & 1;
        float2 cs[8];
        #pragma unroll
        for (int q = 0; q < 8; q++) cs[q] = d_cs[(eb + rrow) * 8 + q];
        #pragma unroll
        for (int hi8 = 0; hi8 < 8; hi8++) {
            int hi = h * 8 + hi8;
            float fhi = 1.f;
            fhi *= (hi & 8) ? -cs[0].y : cs[0].x;
            fhi *= (hi & 4) ? -cs[1].y : cs[1].x;
            fhi *= (hi & 2) ? -cs[2].y : cs[2].x;
            fhi *= (hi & 1) ? -cs[3].y : cs[3].x;
            float A1[2], A2[4], A3[8], A4[16];
            A1[0] = fhi * cs[4].x;  A1[1] = -fhi * cs[4].y;
            #pragma unroll
            for (int i = 0; i < 4; i++)  A2[i] = A1[i >> 1] * ((i & 1) ? -cs[5].y : cs[5].x);
            #pragma unroll
            for (int i = 0; i < 8; i++)  A3[i] = A2[i >> 1] * ((i & 1) ? -cs[6].y : cs[6].x);
            #pragma unroll
            for (int i = 0; i < 16; i++) A4[i] = A3[i >> 1] * ((i & 1) ? -cs[7].y : cs[7].x);
            half2 h2v[8];
            #pragma unroll
            for (int i = 0; i < 8; i++) h2v[i] = __floats2half2_rn(A4[2 * i], A4[2 * i + 1]);
            uint4* dst = (uint4*)&As[rrow * AS_STR + hi * 16];
            dst[0] = *(uint4*)&h2v[0];
            dst[1] = *(uint4*)&h2v[4];
        }
    }
    for (int i = t; i < 128 * 8; i += 256) outs[i] = 0.f;

    // ---- precompute per-lane ldmatrix base addresses (byte offsets) ----
    // A x4 per mt: groups of 8 lanes -> (rows, rows+8, k+8 rows, k+8 rows+8)
    int g = lane >> 3, lr = lane & 7;
    u32 As_base = (u32)__cvta_generic_to_shared(As);
    u32 Bs_base = (u32)__cvta_generic_to_shared(Bs);
    u32 a_addr[2], b_addr[2];
    #pragma unroll
    for (int mt = 0; mt < 2; mt++) {
        int row = wm * 32 + mt * 16 + lr + (g & 1) * 8;
        a_addr[mt] = As_base + (u32)(row * AS_STR + (g >> 1) * 8) * 2;
    }
    #pragma unroll
    for (int p = 0; p < 2; p++) {
        int col = wn * 32 + p * 16 + lr + (g >> 1) * 8;
        b_addr[p] = Bs_base + (u32)(col * BS_STR + (g & 1) * 8) * 2;
    }

    float outp[4][8];
    #pragma unroll
    for (int i = 0; i < 4; i++)
        #pragma unroll
        for (int q = 0; q < 8; q++) outp[i][q] = 0.f;

    for (int ntile = 0; ntile < 8; ntile++) {
        __syncthreads();
        for (int c = t; c < 2048; c += 256) {
            int n = c >> 5, k8 = c & 31;
            *(float4*)&Bs[n * BS_STR + k8 * 8] =
                *(const float4*)&Bh[(ntile * 64 + n) * 256 + k8 * 8];
        }
        __syncthreads();

        float acc[2][4][4];
        #pragma unroll
        for (int mt = 0; mt < 2; mt++)
            #pragma unroll
            for (int nf = 0; nf < 4; nf++)
                #pragma unroll
                for (int rr = 0; rr < 4; rr++) acc[mt][nf][rr] = 0.f;

        #pragma unroll
        for (int ks = 0; ks < 16; ks++) {
            u32 koff = (u32)(ks * 16) * 2;
            u32 a[2][4];
            ldsm_x4(a[0][0], a[0][1], a[0][2], a[0][3], a_addr[0] + koff);
            ldsm_x4(a[1][0], a[1][1], a[1][2], a[1][3], a_addr[1] + koff);
            u32 b[4][2];
            ldsm_x4(b[0][0], b[0][1], b[1][0], b[1][1], b_addr[0] + koff);
            ldsm_x4(b[2][0], b[2][1], b[3][0], b[3][1], b_addr[1] + koff);
            #pragma unroll
            for (int mt = 0; mt < 2; mt++)
                #pragma unroll
                for (int nf = 0; nf < 4; nf++) {
                    asm volatile(
                        "mma.sync.aligned.m16n8k16.row.col.f32.f16.f16.f32 "
                        "{%0,%1,%2,%3}, {%4,%5,%6,%7}, {%8,%9}, {%0,%1,%2,%3};"
                        : "+f"(acc[mt][nf][0]), "+f"(acc[mt][nf][1]),
                          "+f"(acc[mt][nf][2]), "+f"(acc[mt][nf][3])
                        : "r"(a[mt][0]), "r"(a[mt][1]), "r"(a[mt][2]), "r"(a[mt][3]),
                          "r"(b[nf][0]), "r"(b[nf][1]));
                }
        }

        // epilogue: cols (2j, 2j+1) = (Re, Im) in (c0,c1)/(c2,c3)
        #pragma unroll
        for (int mt = 0; mt < 2; mt++)
            #pragma unroll
            for (int nf = 0; nf < 4; nf++) {
                int j = ntile * 32 + wn * 16 + nf * 4 + tig;
                u8 sb = SIGC.v[j];
                float p0 = acc[mt][nf][0] * acc[mt][nf][0] + acc[mt][nf][1] * acc[mt][nf][1];
                float p1 = acc[mt][nf][2] * acc[mt][nf][2] + acc[mt][nf][3] * acc[mt][nf][3];
                #pragma unroll
                for (int q = 0; q < 8; q++) {
                    float s0 = ((sb >> q) & 1) ? -p0 : p0;
                    float s1 = ((sb >> q) & 1) ? -p1 : p1;
                    outp[mt * 2 + 0][q] += s0;
                    outp[mt * 2 + 1][q] += s1;
                }
            }
    }

    #pragma unroll
    for (int idx = 0; idx < 4; idx++) {
        int row = wm * 32 + idx * 8 + gid;
        #pragma unroll
        for (int q = 0; q < 8; q++)
            atomicAdd(&outs[row * 8 + q], outp[idx][q]);
    }
    __syncthreads();

    // ---- fused tail MLP: one thread per row ----
    if (t < 128) {
        float q[8];
        #pragma unroll
        for (int i = 0; i < 8; i++) q[i] = outs[t * 8 + i];

        float h5[16];
        #pragma unroll
        for (int j = 0; j < 16; j++) h5[j] = b5s[j];
        #pragma unroll
        for (int o = 0; o < 32; o++) {
            float a = b4s[o];
            #pragma unroll
            for (int k = 0; k < 8; k++) a += w4s[o * 8 + k] * q[k];
            a = fmaxf(a, 0.f);
            #pragma unroll
            for (int j = 0; j < 16; j++) h5[j] += w5s[j * 32 + o] * a;
        }
        float o6 = b6s[0];
        #pragma unroll
        for (int j = 0; j < 16; j++) o6 += fmaxf(h5[j], 0.f) * w6s[j];
        out[eb + t] = o6;
    }
}

// ================= launch =================
extern "C" void kernel_launch(void* const* d_in, const int* in_sizes, int n_in,
                              void* d_out, int out_size)
{
    const float* x   = (const float*)d_in[0];
    const float* W1  = (const float*)d_in[1];
    const float* b1  = (const float*)d_in[2];
    const float* g1  = (const float*)d_in[3];
    const float* bt1 = (const float*)d_in[4];
    const float* m1  = (const float*)d_in[5];
    const float* v1  = (const float*)d_in[6];
    const float* W2  = (const float*)d_in[7];
    const float* b2  = (const float*)d_in[8];
    const float* g2  = (const float*)d_in[9];
    const float* bt2 = (const float*)d_in[10];
    const float* m2  = (const float*)d_in[11];
    const float* v2  = (const float*)d_in[12];
    const float* W3  = (const float*)d_in[13];
    const float* b3  = (const float*)d_in[14];
    const float* qw  = (const float*)d_in[15];
    const float* W4  = (const float*)d_in[16];
    const float* b4  = (const float*)d_in[17];
    const float* g4  = (const float*)d_in[18];
    const float* bt4 = (const float*)d_in[19];
    const float* m4  = (const float*)d_in[20];
    const float* v4_ = (const float*)d_in[21];
    const float* W5  = (const float*)d_in[22];
    const float* b5  = (const float*)d_in[23];
    const float* W6  = (const float*)d_in[24];
    const float* b6  = (const float*)d_in[25];

    static bool attr_set = false;
    if (!attr_set) {
        cudaFuncSetAttribute(gemm_kernel, cudaFuncAttributeMaxDynamicSharedMemorySize, GSMEM);
        attr_set = true;
    }

    precompute_kernel<<<1, 128>>>(W1, b1, g1, bt1, m1, v1,
                                  W2, b2, g2, bt2, m2, v2,
                                  W4, b4, g4, bt4, m4, v4_, qw);
    build_U_kernel<<<32, 256>>>();
    front_kernel<<<FB, 128>>>(x, W3, b3);
    gemm_kernel<<<BATCH / 128, 256, GSMEM>>>(W5, b5, W6, b6, (float*)d_out);
}

// round 16
// speedup vs baseline: 1.4977x; 1.0392x over previous
#include <cuda_runtime.h>
#include <cuda_fp16.h>
#include <math.h>

#define BATCH 65536
#define NQ 8
#define FULLM 0xffffffffu

typedef unsigned char u8;
typedef unsigned int u32;
typedef unsigned long long ull;

// ================= compile-time GF(2) algebra for CNOT ladder =================
struct M8 { u8 c[8]; };

__host__ __device__ constexpr u8 mv(const M8& m, u8 x) {
    u8 y = 0;
    for (int j = 0; j < 8; j++) if ((x >> j) & 1) y = (u8)(y ^ m.c[j]);
    return y;
}
__host__ __device__ constexpr M8 mm(const M8& a, const M8& b) {
    M8 r{}; for (int j = 0; j < 8; j++) r.c[j] = mv(a, b.c[j]); return r;
}
__host__ __device__ constexpr M8 ident() {
    M8 m{}; for (int j = 0; j < 8; j++) m.c[j] = (u8)(1u << j); return m;
}
__host__ __device__ constexpr M8 ladder() {
    M8 L = ident();
    for (int i = 0; i < 8; i++)
        for (int j = i + 1; j < 8; j++) {
            int cb = 7 - i, tb = 7 - j;
            M8 P = ident();
            P.c[cb] = (u8)((1u << cb) | (1u << tb));
            L = mm(L, P);
        }
    return L;
}
__host__ __device__ constexpr M8 minv(const M8& a) {
    u8 row[8] = {}, inv[8] = {};
    for (int i = 0; i < 8; i++) inv[i] = (u8)(1u << i);
    for (int i = 0; i < 8; i++)
        for (int j = 0; j < 8; j++)
            if ((a.c[j] >> i) & 1) row[i] = (u8)(row[i] | (1u << j));
    for (int col = 0; col < 8; col++) {
        int piv = col;
        while (!((row[piv] >> col) & 1)) piv++;
        u8 t = row[col]; row[col] = row[piv]; row[piv] = t;
        t = inv[col]; inv[col] = inv[piv]; inv[piv] = t;
        for (int i = 0; i < 8; i++)
            if (i != col && ((row[i] >> col) & 1)) { row[i] = (u8)(row[i] ^ row[col]); inv[i] = (u8)(inv[i] ^ inv[col]); }
    }
    M8 r{};
    for (int i = 0; i < 8; i++)
        for (int j = 0; j < 8; j++)
            if ((inv[i] >> j) & 1) r.c[j] = (u8)(r.c[j] | (1u << i));
    return r;
}
__host__ __device__ constexpr int par8(int x) { x ^= x >> 4; x ^= x >> 2; x ^= x >> 1; return x & 1; }

struct Masks {
    u8 v[3][8];
    u8 r[3][8];
    u8 rf[8];
};
__host__ __device__ constexpr Masks make_masks() {
    Masks mk{};
    M8 L = ladder();
    M8 C = ident();
    for (int l = 0; l < 3; l++) {
        M8 Ci = minv(C);
        for (int q = 0; q < 8; q++) {
            int B = 7 - q;
            mk.v[l][q] = mv(C, (u8)(1u << B));
            u8 rr = 0;
            for (int j = 0; j < 8; j++) if ((Ci.c[j] >> B) & 1) rr = (u8)(rr | (1u << j));
            mk.r[l][q] = rr;
        }
        C = mm(C, L);
    }
    M8 Cf = minv(C);
    for (int q = 0; q < 8; q++) {
        int B = 7 - q;
        u8 rr = 0;
        for (int j = 0; j < 8; j++) if ((Cf.c[j] >> B) & 1) rr = (u8)(rr | (1u << j));
        mk.rf[q] = rr;
    }
    return mk;
}
constexpr Masks MK = make_masks();

__host__ __device__ constexpr bool masks_ok() {
    constexpr Masks mk = make_masks();
    M8 L = ladder();
    M8 C = ident();
    for (int l = 0; l < 3; l++) {
        M8 Ci = minv(C);
        M8 P = mm(C, Ci);
        for (int j = 0; j < 8; j++) if (P.c[j] != (u8)(1u << j)) return false;
        for (int q = 0; q < 8; q++)
            if (par8(mk.v[l][q] & mk.r[l][q]) != 1) return false;
        C = mm(C, L);
    }
    return true;
}
static_assert(masks_ok(), "GF(2) mask algebra broken");

// sign LUT: SIG.v[j] bit q = parity(j & rf[q])
struct SigT { u8 v[256]; };
__host__ __device__ constexpr SigT make_sig() {
    SigT s{};
    Masks mk = make_masks();
    for (int j = 0; j < 256; j++) {
        u8 b = 0;
        for (int q = 0; q < 8; q++) if (par8(j & mk.rf[q])) b = (u8)(b | (1u << q));
        s.v[j] = b;
    }
    return s;
}
__constant__ SigT SIGC = make_sig();

// ================= f32x2 / smem helpers =================
__device__ __forceinline__ ull fpk(float lo, float hi) {
    ull r; asm("mov.b64 %0, {%1,%2};" : "=l"(r) : "f"(lo), "f"(hi)); return r;
}
__device__ __forceinline__ void funpk(ull v, float& lo, float& hi) {
    asm("mov.b64 {%0,%1}, %2;" : "=f"(lo), "=f"(hi) : "l"(v));
}
__device__ __forceinline__ ull mul2(ull a, ull b) {
    ull d; asm("mul.rn.f32x2 %0, %1, %2;" : "=l"(d) : "l"(a), "l"(b)); return d;
}
__device__ __forceinline__ ull fma2(ull a, ull b, ull c) {
    ull d; asm("fma.rn.f32x2 %0, %1, %2, %3;" : "=l"(d) : "l"(a), "l"(b), "l"(c)); return d;
}
__device__ __forceinline__ float psum(ull v) {
    float lo, hi; funpk(v, lo, hi); return lo + hi;
}
// packed dot-step: acc += w4 .* h4 (pairwise lanes)
__device__ __forceinline__ ull dot4(ull acc, float4 w, float4 h) {
    acc = fma2(fpk(w.x, w.y), fpk(h.x, h.y), acc);
    acc = fma2(fpk(w.z, w.w), fpk(h.z, h.w), acc);
    return acc;
}
__device__ __forceinline__ void ldsm_x4(u32& r0, u32& r1, u32& r2, u32& r3, u32 addr) {
    asm volatile("ldmatrix.sync.aligned.m8n8.x4.shared.b16 {%0,%1,%2,%3}, [%4];"
                 : "=r"(r0), "=r"(r1), "=r"(r2), "=r"(r3) : "r"(addr));
}

struct GatePack { ull AR, AIp, AIn, BRp, BRn, BIp, BIn, pad; };

// ================= device scratch =================
__device__ float    d_W1f[128 * 16];
__device__ float    d_b1f[128];
__device__ float4   d_W2f4[64 * 32];
__device__ float    d_b2f[64];
__device__ float    d_W4f[32 * 8];
__device__ float    d_b4f[32];
__device__ GatePack d_qgp[24];
__device__ float2   d_cs[BATCH * NQ];               // (cos th/2, sin th/2)
__device__ uint4    d_BhR[512 * 32];                // B fp16 [512 n][256 k] (256KB)

// ================= precompute =================
__global__ void precompute_kernel(
    const float* W1, const float* b1, const float* g1, const float* bt1, const float* m1, const float* v1,
    const float* W2, const float* b2, const float* g2, const float* bt2, const float* m2, const float* v2,
    const float* W4, const float* b4, const float* g4, const float* bt4, const float* m4, const float* v4,
    const float* qw)
{
    int t = threadIdx.x;  // 128
    if (t < 128) {
        float a = g1[t] * rsqrtf(v1[t] + 1e-5f);
        for (int k = 0; k < 16; k++) d_W1f[t * 16 + k] = W1[t * 16 + k] * a;
        d_b1f[t] = (b1[t] - m1[t]) * a + bt1[t];
    }
    if (t < 64) {
        float a = g2[t] * rsqrtf(v2[t] + 1e-5f);
        float* w2 = (float*)d_W2f4;
        for (int k = 0; k < 128; k++) w2[t * 128 + k] = W2[t * 128 + k] * a;
        d_b2f[t] = (b2[t] - m2[t]) * a + bt2[t];
    }
    if (t < 32) {
        float a = g4[t] * rsqrtf(v4[t] + 1e-5f);
        for (int k = 0; k < 8; k++) d_W4f[t * 8 + k] = W4[t * 8 + k] * a;
        d_b4f[t] = (b4[t] - m4[t]) * a + bt4[t];
    }
    if (t < 24) {
        float sx, cx, sy, cy, sz, cz;
        sincosf(0.5f * qw[t * 3 + 0], &sx, &cx);
        sincosf(0.5f * qw[t * 3 + 1], &sy, &cy);
        sincosf(0.5f * qw[t * 3 + 2], &sz, &cz);
        float cycx = cy * cx, sysx = sy * sx, sycx = sy * cx, cysx = cy * sx;
        float ar  = cz * cycx - sz * sysx;
        float ai0 = -(cz * sysx + sz * cycx);
        float br0 = cz * sycx - sz * cysx;
        float bi  = -(cz * cysx + sz * sycx);
        Masks mk = make_masks();
        int l = t >> 3, q = t & 7;
        int rr = mk.r[l][q] & 7;
        float tau = (rr & 1) ? -1.f : 1.f;
        GatePack g;
        g.AR  = fpk(ar, ar);
        g.AIp = fpk(ai0,  tau * ai0);
        g.AIn = fpk(-ai0, -tau * ai0);
        g.BRp = fpk(br0,  tau * br0);
        g.BRn = fpk(-br0, -tau * br0);
        g.BIp = fpk(bi, bi);
        g.BIn = fpk(-bi, -bi);
        g.pad = 0;
        d_qgp[t] = g;
    }
}

// ================= packed gate machinery (verified) =================
template<int X> struct Par {
    static constexpr int val =
        ((X >> 7) ^ (X >> 6) ^ (X >> 5) ^ (X >> 4) ^ (X >> 3) ^ (X >> 2) ^ (X >> 1) ^ X) & 1;
};

template<int V, int R>
__device__ __forceinline__ void gate2(ull X[4], ull Y[4], const GatePack* gp, int lane)
{
    static_assert(Par<V & R>::val == 1, "pair/branch masks inconsistent");
    constexpr int vl = (V >> 3) & 31, vr = V & 7;
    constexpr int rl = (R >> 3) & 31, rr = R & 7;

    ull AR  = gp->AR;
    ull BIp = gp->BIp;
    ull BIn = gp->BIn;
    bool lp = (__popc(lane & rl) & 1) != 0;
    ull AIpf = lp ? gp->AIn : gp->AIp;
    ull AInf = lp ? gp->AIp : gp->AIn;
    ull BRpf = lp ? gp->BRn : gp->BRp;
    ull BRnf = lp ? gp->BRp : gp->BRn;

    ull PX[4], PY[4];
    #pragma unroll
    for (int k = 0; k < 4; k++) {
        const int kp = k ^ (vr >> 1);
        if constexpr ((vr & 1) != 0) {
            float xlo, xhi, ylo, yhi;
            funpk(X[kp], xlo, xhi);
            funpk(Y[kp], ylo, yhi);
            if constexpr (vl != 0) {
                xlo = __shfl_xor_sync(FULLM, xlo, vl);
                xhi = __shfl_xor_sync(FULLM, xhi, vl);
                ylo = __shfl_xor_sync(FULLM, ylo, vl);
                yhi = __shfl_xor_sync(FULLM, yhi, vl);
            }
            PX[k] = fpk(xhi, xlo);
            PY[k] = fpk(yhi, ylo);
        } else {
            if constexpr (vl != 0) {
                PX[k] = __shfl_xor_sync(FULLM, X[kp], vl);
                PY[k] = __shfl_xor_sync(FULLM, Y[kp], vl);
            } else {
                PX[k] = X[kp];
                PY[k] = Y[kp];
            }
        }
    }
    #pragma unroll
    for (int k = 0; k < 4; k++) {
        const bool s0 = ((__popc((2 * k) & rr) & 1) != 0);
        ull AIx = s0 ? AIpf : AInf;
        ull AIy = s0 ? AInf : AIpf;
        ull BR  = s0 ? BRnf : BRpf;
        ull t1 = mul2(X[k], AR);
        t1 = fma2(Y[k],  AIx, t1);
        t1 = fma2(PX[k], BR,  t1);
        t1 = fma2(PY[k], BIn, t1);
        ull t2 = mul2(Y[k], AR);
        t2 = fma2(X[k],  AIy, t2);
        t2 = fma2(PY[k], BR,  t2);
        t2 = fma2(PX[k], BIp, t2);
        X[k] = t1; Y[k] = t2;
    }
}

template<int L, int Q>
__device__ __forceinline__ void gate(ull X[4], ull Y[4], const GatePack* gs, int lane)
{
    gate2<MK.v[L][Q], MK.r[L][Q]>(X, Y, gs + (L * 8 + Q), lane);
}

// ================= build U: warp k simulates basis k; B stored [n=512][k=256] fp16 =================
__global__ void __launch_bounds__(256) build_U_kernel()
{
    __shared__ GatePack gs[24];
    __shared__ half Bst[512][8];
    int t = threadIdx.x;
    if (t < 192) ((ull*)gs)[t] = ((const ull*)d_qgp)[t];
    __syncthreads();

    int w = t >> 5;
    int k = blockIdx.x * 8 + w;
    int lane = t & 31;

    ull X[4], Y[4];
    #pragma unroll
    for (int p = 0; p < 4; p++) {
        int j0 = lane * 8 + 2 * p, j1 = j0 + 1;
        X[p] = fpk(j0 == k ? 1.f : 0.f, j1 == k ? 1.f : 0.f);
        Y[p] = fpk(0.f, 0.f);
    }

    gate<0,0>(X, Y, gs, lane); gate<0,1>(X, Y, gs, lane); gate<0,2>(X, Y, gs, lane); gate<0,3>(X, Y, gs, lane);
    gate<0,4>(X, Y, gs, lane); gate<0,5>(X, Y, gs, lane); gate<0,6>(X, Y, gs, lane); gate<0,7>(X, Y, gs, lane);
    gate<1,0>(X, Y, gs, lane); gate<1,1>(X, Y, gs, lane); gate<1,2>(X, Y, gs, lane); gate<1,3>(X, Y, gs, lane);
    gate<1,4>(X, Y, gs, lane); gate<1,5>(X, Y, gs, lane); gate<1,6>(X, Y, gs, lane); gate<1,7>(X, Y, gs, lane);
    gate<2,0>(X, Y, gs, lane); gate<2,1>(X, Y, gs, lane); gate<2,2>(X, Y, gs, lane); gate<2,3>(X, Y, gs, lane);
    gate<2,4>(X, Y, gs, lane); gate<2,5>(X, Y, gs, lane); gate<2,6>(X, Y, gs, lane); gate<2,7>(X, Y, gs, lane);

    #pragma unroll
    for (int p = 0; p < 4; p++) {
        float x0, x1, y0, y1;
        funpk(X[p], x0, x1);
        funpk(Y[p], y0, y1);
        int j0 = lane * 8 + 2 * p, j1 = j0 + 1;
        Bst[2 * j0][w]     = __float2half_rn(x0);
        Bst[2 * j0 + 1][w] = __float2half_rn(y0);
        Bst[2 * j1][w]     = __float2half_rn(x1);
        Bst[2 * j1 + 1][w] = __float2half_rn(y1);
    }
    __syncthreads();

    half* Bh = (half*)d_BhR;
    for (int i = t; i < 512; i += 256)
        *(uint4*)&Bh[i * 256 + blockIdx.x * 8] = *(uint4*)&Bst[i][0];
}

// ================= front MLP (f32x2-packed): x[B,16] -> cs pairs =================
#define FB 2048
#define FROWS 32
#define FTILE 16

__global__ void __launch_bounds__(128) front_kernel(const float* __restrict__ x,
                                                    const float* __restrict__ W3,
                                                    const float* __restrict__ b3)
{
    __shared__ float4 w2s4[64 * 32];
    __shared__ float4 w3s4[8 * 16];
    __shared__ float4 xs4[FTILE][4];
    __shared__ float4 h1s4[FTILE][32];
    __shared__ float4 h2s4[FTILE][16];
    __shared__ float  b2s[64], b3s[8];

    int t = threadIdx.x;  // 128
    for (int i = t; i < 64 * 32; i += 128) {
        int o = i >> 5, k = i & 31;
        w2s4[(o << 5) + (k ^ (o & 7))] = d_W2f4[i];
    }
    {
        const float4* W34 = (const float4*)W3;
        if (t < 8 * 16) w3s4[t] = W34[t];
        if (t < 64) b2s[t] = d_b2f[t];
        if (t < 8)  b3s[t] = b3[t];
    }
    // W1 row as 4 float4 (packed in dot4)
    float4 w1v[4];
    #pragma unroll
    for (int j = 0; j < 4; j++) w1v[j] = *(const float4*)&d_W1f[t * 16 + j * 4];
    float bb1 = d_b1f[t];
    __syncthreads();

    const float4* x4 = (const float4*)x;
    int base = blockIdx.x * FROWS;

    for (int it = 0; it < FROWS / FTILE; it++) {
        int rbase = base + it * FTILE;
        if (t < FTILE * 4) xs4[t >> 2][t & 3] = x4[(rbase + (t >> 2)) * 4 + (t & 3)];
        __syncthreads();

        // layer 1: thread = neuron, 16 rows, packed k-pairs
        #pragma unroll
        for (int r = 0; r < FTILE; r++) {
            ull accp = fpk(0.f, 0.f);
            accp = dot4(accp, w1v[0], xs4[r][0]);
            accp = dot4(accp, w1v[1], xs4[r][1]);
            accp = dot4(accp, w1v[2], xs4[r][2]);
            accp = dot4(accp, w1v[3], xs4[r][3]);
            ((float*)&h1s4[r][0])[t] = fmaxf(bb1 + psum(accp), 0.f);
        }
        __syncthreads();

        // layer 2: o = t&63, rows half_*8 .. +7, packed k-pairs
        {
            int o = t & 63, half_ = t >> 6;
            int obase = o << 5, osw = o & 7;
            ull acc2[8];
            #pragma unroll
            for (int rr = 0; rr < 8; rr++) acc2[rr] = fpk(0.f, 0.f);
            #pragma unroll 4
            for (int k4 = 0; k4 < 32; k4++) {
                float4 w = w2s4[obase + (k4 ^ osw)];   // logical [o][k4]
                ull wlo = fpk(w.x, w.y), whi = fpk(w.z, w.w);
                #pragma unroll
                for (int rr = 0; rr < 8; rr++) {
                    float4 h = h1s4[half_ * 8 + rr][k4];
                    acc2[rr] = fma2(fpk(h.x, h.y), wlo, acc2[rr]);
                    acc2[rr] = fma2(fpk(h.z, h.w), whi, acc2[rr]);
                }
            }
            float b2v = b2s[o];
            #pragma unroll
            for (int rr = 0; rr < 8; rr++)
                ((float*)&h2s4[half_ * 8 + rr][0])[o] = fmaxf(b2v + psum(acc2[rr]), 0.f);
        }
        __syncthreads();

        // layer 3: r = t>>3 (16 rows), o = t&7, packed + tanh
        {
            int r = t >> 3, o = t & 7;
            ull accp = fpk(0.f, 0.f);
            #pragma unroll
            for (int k4 = 0; k4 < 16; k4++)
                accp = dot4(accp, w3s4[o * 16 + k4], h2s4[r][k4]);
            float pre = tanhf(b3s[o] + psum(accp));
            float sc, cc;
            __sincosf(0.5f * pre, &sc, &cc);
            d_cs[(rbase + r) * 8 + o] = make_float2(cc, sc);
        }
        __syncthreads();
    }
}

// ================= fused GEMM (ldmatrix fragments) =================
#define AS_STR 264
#define BS_STR 264
#define GSMEM (128 * AS_STR * 2 + 64 * BS_STR * 2 + 128 * 8 * 4)

__global__ void __launch_bounds__(256, 2) gemm_kernel(
    const float* __restrict__ W5, const float* __restrict__ b5,
    const float* __restrict__ W6, const float* __restrict__ b6,
    float* __restrict__ out)
{
    extern __shared__ char smem[];
    half*  As   = (half*)smem;                          // [128][264]
    half*  Bs   = As + 128 * AS_STR;                    // [64][264]
    float* outs = (float*)(Bs + 64 * BS_STR);           // [128*8]
    __shared__ float w4s[32 * 8], b4s[32], w5s[16 * 32], b5s[16], w6s[16], b6s[1];

    int t = threadIdx.x;
    int warp = t >> 5, lane = t & 31;
    int gid = lane >> 2, tig = lane & 3;
    int wm = warp & 3, wn = warp >> 2;
    int eb = blockIdx.x * 128;

    const half* Bh = (const half*)d_BhR;

    // ---- stage tail weights ----
    w4s[t] = d_W4f[t];
    if (t < 32) b4s[t] = d_b4f[t];
    for (int i = t; i < 16 * 32; i += 256) w5s[i] = W5[i];
    if (t < 16) { b5s[t] = b5[t]; w6s[t] = W6[t]; }
    if (t == 0) b6s[0] = b6[0];

    // ---- build A tile in smem ----
    {
        int rrow = t >> 1, h = t & 1;
        float2 cs[8];
        #pragma unroll
        for (int q = 0; q < 8; q++) cs[q] = d_cs[(eb + rrow) * 8 + q];
        #pragma unroll
        for (int hi8 = 0; hi8 < 8; hi8++) {
            int hi = h * 8 + hi8;
            float fhi = 1.f;
            fhi *= (hi & 8) ? -cs[0].y : cs[0].x;
            fhi *= (hi & 4) ? -cs[1].y : cs[1].x;
            fhi *= (hi & 2) ? -cs[2].y : cs[2].x;
            fhi *= (hi & 1) ? -cs[3].y : cs[3].x;
            float A1[2], A2[4], A3[8], A4[16];
            A1[0] = fhi * cs[4].x;  A1[1] = -fhi * cs[4].y;
            #pragma unroll
            for (int i = 0; i < 4; i++)  A2[i] = A1[i >> 1] * ((i & 1) ? -cs[5].y : cs[5].x);
            #pragma unroll
            for (int i = 0; i < 8; i++)  A3[i] = A2[i >> 1] * ((i & 1) ? -cs[6].y : cs[6].x);
            #pragma unroll
            for (int i = 0; i < 16; i++) A4[i] = A3[i >> 1] * ((i & 1) ? -cs[7].y : cs[7].x);
            half2 h2v[8];
            #pragma unroll
            for (int i = 0; i < 8; i++) h2v[i] = __floats2half2_rn(A4[2 * i], A4[2 * i + 1]);
            uint4* dst = (uint4*)&As[rrow * AS_STR + hi * 16];
            dst[0] = *(uint4*)&h2v[0];
            dst[1] = *(uint4*)&h2v[4];
        }
    }
    for (int i = t; i < 128 * 8; i += 256) outs[i] = 0.f;

    // ---- precompute per-lane ldmatrix base addresses ----
    int g = lane >> 3, lr = lane & 7;
    u32 As_base = (u32)__cvta_generic_to_shared(As);
    u32 Bs_base = (u32)__cvta_generic_to_shared(Bs);
    u32 a_addr[2], b_addr[2];
    #pragma unroll
    for (int mt = 0; mt < 2; mt++) {
        int row = wm * 32 + mt * 16 + lr + (g & 1) * 8;
        a_addr[mt] = As_base + (u32)(row * AS_STR + (g >> 1) * 8) * 2;
    }
    #pragma unroll
    for (int p = 0; p < 2; p++) {
        int col = wn * 32 + p * 16 + lr + (g >> 1) * 8;
        b_addr[p] = Bs_base + (u32)(col * BS_STR + (g & 1) * 8) * 2;
    }

    float outp[4][8];
    #pragma unroll
    for (int i = 0; i < 4; i++)
        #pragma unroll
        for (int q = 0; q < 8; q++) outp[i][q] = 0.f;

    for (int ntile = 0; ntile < 8; ntile++) {
        __syncthreads();
        for (int c = t; c < 2048; c += 256) {
            int n = c >> 5, k8 = c & 31;
            *(float4*)&Bs[n * BS_STR + k8 * 8] =
                *(const float4*)&Bh[(ntile * 64 + n) * 256 + k8 * 8];
        }
        __syncthreads();

        float acc[2][4][4];
        #pragma unroll
        for (int mt = 0; mt < 2; mt++)
            #pragma unroll
            for (int nf = 0; nf < 4; nf++)
                #pragma unroll
                for (int rr = 0; rr < 4; rr++) acc[mt][nf][rr] = 0.f;

        #pragma unroll
        for (int ks = 0; ks < 16; ks++) {
            u32 koff = (u32)(ks * 16) * 2;
            u32 a[2][4];
            ldsm_x4(a[0][0], a[0][1], a[0][2], a[0][3], a_addr[0] + koff);
            ldsm_x4(a[1][0], a[1][1], a[1][2], a[1][3], a_addr[1] + koff);
            u32 b[4][2];
            ldsm_x4(b[0][0], b[0][1], b[1][0], b[1][1], b_addr[0] + koff);
            ldsm_x4(b[2][0], b[2][1], b[3][0], b[3][1], b_addr[1] + koff);
            #pragma unroll
            for (int mt = 0; mt < 2; mt++)
                #pragma unroll
                for (int nf = 0; nf < 4; nf++) {
                    asm volatile(
                        "mma.sync.aligned.m16n8k16.row.col.f32.f16.f16.f32 "
                        "{%0,%1,%2,%3}, {%4,%5,%6,%7}, {%8,%9}, {%0,%1,%2,%3};"
                        : "+f"(acc[mt][nf][0]), "+f"(acc[mt][nf][1]),
                          "+f"(acc[mt][nf][2]), "+f"(acc[mt][nf][3])
                        : "r"(a[mt][0]), "r"(a[mt][1]), "r"(a[mt][2]), "r"(a[mt][3]),
                          "r"(b[nf][0]), "r"(b[nf][1]));
                }
        }

        // epilogue: cols (2j, 2j+1) = (Re, Im) in (c0,c1)/(c2,c3)
        #pragma unroll
        for (int mt = 0; mt < 2; mt++)
            #pragma unroll
            for (int nf = 0; nf < 4; nf++) {
                int j = ntile * 32 + wn * 16 + nf * 4 + tig;
                u8 sb = SIGC.v[j];
                float p0 = acc[mt][nf][0] * acc[mt][nf][0] + acc[mt][nf][1] * acc[mt][nf][1];
                float p1 = acc[mt][nf][2] * acc[mt][nf][2] + acc[mt][nf][3] * acc[mt][nf][3];
                #pragma unroll
                for (int q = 0; q < 8; q++) {
                    float s0 = ((sb >> q) & 1) ? -p0 : p0;
                    float s1 = ((sb >> q) & 1) ? -p1 : p1;
                    outp[mt * 2 + 0][q] += s0;
                    outp[mt * 2 + 1][q] += s1;
                }
            }
    }

    #pragma unroll
    for (int idx = 0; idx < 4; idx++) {
        int row = wm * 32 + idx * 8 + gid;
        #pragma unroll
        for (int q = 0; q < 8; q++)
            atomicAdd(&outs[row * 8 + q], outp[idx][q]);
    }
    __syncthreads();

    // ---- fused tail MLP: one thread per row ----
    if (t < 128) {
        float q[8];
        #pragma unroll
        for (int i = 0; i < 8; i++) q[i] = outs[t * 8 + i];

        float h5[16];
        #pragma unroll
        for (int j = 0; j < 16; j++) h5[j] = b5s[j];
        #pragma unroll
        for (int o = 0; o < 32; o++) {
            float a = b4s[o];
            #pragma unroll
            for (int k = 0; k < 8; k++) a += w4s[o * 8 + k] * q[k];
            a = fmaxf(a, 0.f);
            #pragma unroll
            for (int j = 0; j < 16; j++) h5[j] += w5s[j * 32 + o] * a;
        }
        float o6 = b6s[0];
        #pragma unroll
        for (int j = 0; j < 16; j++) o6 += fmaxf(h5[j], 0.f) * w6s[j];
        out[eb + t] = o6;
    }
}

// ================= launch =================
extern "C" void kernel_launch(void* const* d_in, const int* in_sizes, int n_in,
                              void* d_out, int out_size)
{
    const float* x   = (const float*)d_in[0];
    const float* W1  = (const float*)d_in[1];
    const float* b1  = (const float*)d_in[2];
    const float* g1  = (const float*)d_in[3];
    const float* bt1 = (const float*)d_in[4];
    const float* m1  = (const float*)d_in[5];
    const float* v1  = (const float*)d_in[6];
    const float* W2  = (const float*)d_in[7];
    const float* b2  = (const float*)d_in[8];
    const float* g2  = (const float*)d_in[9];
    const float* bt2 = (const float*)d_in[10];
    const float* m2  = (const float*)d_in[11];
    const float* v2  = (const float*)d_in[12];
    const float* W3  = (const float*)d_in[13];
    const float* b3  = (const float*)d_in[14];
    const float* qw  = (const float*)d_in[15];
    const float* W4  = (const float*)d_in[16];
    const float* b4  = (const float*)d_in[17];
    const float* g4  = (const float*)d_in[18];
    const float* bt4 = (const float*)d_in[19];
    const float* m4  = (const float*)d_in[20];
    const float* v4_ = (const float*)d_in[21];
    const float* W5  = (const float*)d_in[22];
    const float* b5  = (const float*)d_in[23];
    const float* W6  = (const float*)d_in[24];
    const float* b6  = (const float*)d_in[25];

    static bool attr_set = false;
    if (!attr_set) {
        cudaFuncSetAttribute(gemm_kernel, cudaFuncAttributeMaxDynamicSharedMemorySize, GSMEM);
        attr_set = true;
    }

    precompute_kernel<<<1, 128>>>(W1, b1, g1, bt1, m1, v1,
                                  W2, b2, g2, bt2, m2, v2,
                                  W4, b4, g4, bt4, m4, v4_, qw);
    build_U_kernel<<<32, 256>>>();
    front_kernel<<<FB, 128>>>(x, W3, b3);
    gemm_kernel<<<BATCH / 128, 256, GSMEM>>>(W5, b5, W6, b6, (float*)d_out);
}